// round 1
// baseline (speedup 1.0000x reference)
#include <cuda_runtime.h>

#define B_  2
#define T_  2048
#define S_  2048
#define H_  16
#define HD_ 64
#define DM_ 1024

// Scratch (allocation-free rule: __device__ globals)
__device__ float g_q[B_*T_*H_*HD_];
__device__ float g_k[B_*S_*H_*HD_];
__device__ float g_v[B_*S_*H_*HD_];
__device__ float g_o[B_*T_*H_*HD_];

// ---------------------------------------------------------------------------
// SGEMM: C[M,N] = A[M,K] @ B[K,N], all row-major fp32.
// 128x64 block tile, BK=16, 256 threads, 8x4 per-thread microtile.
// ---------------------------------------------------------------------------
#define BM 128
#define BN 64
#define BK 16

__global__ __launch_bounds__(256)
void sgemm_kernel(const float* __restrict__ A, const float* __restrict__ B,
                  float* __restrict__ C, int M, int N, int K) {
    __shared__ float As[BK][BM + 4];   // A stored transposed (k-major)
    __shared__ float Bs[BK][BN];

    const int tid = threadIdx.x;
    const int tx = tid & 15;          // 0..15 -> 4 output cols each
    const int ty = tid >> 4;          // 0..15 -> 8 output rows each
    const int bm = blockIdx.y * BM;
    const int bn = blockIdx.x * BN;

    float acc[8][4];
    #pragma unroll
    for (int i = 0; i < 8; i++)
        #pragma unroll
        for (int j = 0; j < 4; j++) acc[i][j] = 0.f;

    for (int k0 = 0; k0 < K; k0 += BK) {
        // Load A tile (128x16) as float4, store transposed
        #pragma unroll
        for (int i = 0; i < 2; i++) {
            int idx = tid + i * 256;          // 0..511
            int row = idx >> 2;               // 0..127
            int c4  = (idx & 3) << 2;         // 0,4,8,12
            float4 va = *(const float4*)&A[(bm + row) * K + k0 + c4];
            As[c4 + 0][row] = va.x;
            As[c4 + 1][row] = va.y;
            As[c4 + 2][row] = va.z;
            As[c4 + 3][row] = va.w;
        }
        // Load B tile (16x64) as float4
        {
            int row = tid >> 4;               // 0..15
            int c4  = (tid & 15) << 2;        // 0..60
            *(float4*)&Bs[row][c4] = *(const float4*)&B[(k0 + row) * N + bn + c4];
        }
        __syncthreads();

        #pragma unroll
        for (int kk = 0; kk < BK; kk++) {
            float a[8], bb[4];
            *(float4*)&a[0] = *(const float4*)&As[kk][ty * 8];
            *(float4*)&a[4] = *(const float4*)&As[kk][ty * 8 + 4];
            *(float4*)&bb[0] = *(const float4*)&Bs[kk][tx * 4];
            #pragma unroll
            for (int i = 0; i < 8; i++)
                #pragma unroll
                for (int j = 0; j < 4; j++)
                    acc[i][j] += a[i] * bb[j];
        }
        __syncthreads();
    }

    #pragma unroll
    for (int i = 0; i < 8; i++) {
        float4 v = make_float4(acc[i][0], acc[i][1], acc[i][2], acc[i][3]);
        *(float4*)&C[(bm + ty * 8 + i) * N + bn + tx * 4] = v;
    }
}

// ---------------------------------------------------------------------------
// Partial RoPE on first 32 dims of each 64-dim head, rotate-half with half=16.
// One thread handles one (b, pos, h, d) pair -> dims d and d+16.
// Total threads = B * 2048 * 16 * 16 = 2^20.
// ---------------------------------------------------------------------------
__global__ void rope_kernel(float* __restrict__ t,
                            const float* __restrict__ cosb,
                            const float* __restrict__ sinb) {
    int idx = blockIdx.x * blockDim.x + threadIdx.x;
    int d   = idx & 15;
    int h   = (idx >> 4) & (H_ - 1);
    int pos = (idx >> 8) & (T_ - 1);
    int b   = idx >> 19;
    float* base = t + ((b * T_ + pos) * H_ + h) * HD_;
    float c = cosb[pos * 16 + d];
    float s = sinb[pos * 16 + d];
    float x1 = base[d];
    float x2 = base[d + 16];
    base[d]      = x1 * c - x2 * s;
    base[d + 16] = x2 * c + x1 * s;
}

// ---------------------------------------------------------------------------
// Flash attention, fp32, online softmax.
// Block = (64 q-rows, one head, one batch). 256 threads: thread (ty,tx)
// owns 4 q-rows x 4 cols. K tile kept d-major (transposed) in smem so the
// score loop reads conflict-free float4 across keys.
// ---------------------------------------------------------------------------
#define TQ 64
#define TS 64
#define DPAD 68
#define FA_SMEM (4 * 64 * DPAD * 4)   // qs + kst + vs + ps

__global__ __launch_bounds__(256, 2)
void flash_attn_kernel(const float* __restrict__ q, const float* __restrict__ k,
                       const float* __restrict__ v, const float* __restrict__ mask,
                       float* __restrict__ o) {
    extern __shared__ float sm[];
    float* qs  = sm;                  // [64][68]  q (pre-scaled)
    float* kst = sm + 64 * DPAD;      // [68 d rows][64 keys] (d-major)
    float* vs  = sm + 2 * 64 * DPAD;  // [64 keys][68]
    float* ps  = sm + 3 * 64 * DPAD;  // [64 q][68] probabilities

    const int t0  = blockIdx.x * TQ;
    const int h   = blockIdx.y;
    const int b   = blockIdx.z;
    const int tid = threadIdx.x;
    const int tx  = tid & 15, ty = tid >> 4;
    const int r0  = ty * 4, c0 = tx * 4;

    // Load Q tile once, fold in softmax scale 1/sqrt(64) = 0.125
    #pragma unroll
    for (int i = 0; i < 4; i++) {
        int idx = tid + i * 256;
        int row = idx >> 4;
        int d4  = (idx & 15) << 2;
        float4 vq = *(const float4*)&q[((b * T_ + t0 + row) * H_ + h) * HD_ + d4];
        float* dst = &qs[row * DPAD + d4];
        dst[0] = vq.x * 0.125f; dst[1] = vq.y * 0.125f;
        dst[2] = vq.z * 0.125f; dst[3] = vq.w * 0.125f;
    }

    float m_i[4], l_i[4], acc[4][4];
    #pragma unroll
    for (int i = 0; i < 4; i++) {
        m_i[i] = -1e30f; l_i[i] = 0.f;
        #pragma unroll
        for (int j = 0; j < 4; j++) acc[i][j] = 0.f;
    }

    for (int s0 = 0; s0 < S_; s0 += TS) {
        __syncthreads();   // previous iter consumers done before overwrite

        // Load K tile (d-major) and V tile
        #pragma unroll
        for (int i = 0; i < 4; i++) {
            int idx = tid + i * 256;
            int row = idx >> 4;               // key index j
            int d4  = (idx & 15) << 2;
            float4 vk = *(const float4*)&k[((b * S_ + s0 + row) * H_ + h) * HD_ + d4];
            kst[(d4 + 0) * DPAD + row] = vk.x;
            kst[(d4 + 1) * DPAD + row] = vk.y;
            kst[(d4 + 2) * DPAD + row] = vk.z;
            kst[(d4 + 3) * DPAD + row] = vk.w;
            float4 vv = *(const float4*)&v[((b * S_ + s0 + row) * H_ + h) * HD_ + d4];
            *(float4*)&vs[row * DPAD + d4] = vv;
        }
        __syncthreads();

        // Scores: s_[i][j] = (q*scale) . k  + mask
        float s_[4][4];
        #pragma unroll
        for (int i = 0; i < 4; i++) {
            float4 mk = *(const float4*)&mask[(b * T_ + t0 + r0 + i) * S_ + s0 + c0];
            s_[i][0] = mk.x; s_[i][1] = mk.y; s_[i][2] = mk.z; s_[i][3] = mk.w;
        }
        for (int d4 = 0; d4 < HD_; d4 += 4) {
            float4 kv0 = *(const float4*)&kst[(d4 + 0) * DPAD + c0];
            float4 kv1 = *(const float4*)&kst[(d4 + 1) * DPAD + c0];
            float4 kv2 = *(const float4*)&kst[(d4 + 2) * DPAD + c0];
            float4 kv3 = *(const float4*)&kst[(d4 + 3) * DPAD + c0];
            #pragma unroll
            for (int i = 0; i < 4; i++) {
                float4 qv = *(const float4*)&qs[(r0 + i) * DPAD + d4];
                s_[i][0] += qv.x*kv0.x + qv.y*kv1.x + qv.z*kv2.x + qv.w*kv3.x;
                s_[i][1] += qv.x*kv0.y + qv.y*kv1.y + qv.z*kv2.y + qv.w*kv3.y;
                s_[i][2] += qv.x*kv0.z + qv.y*kv1.z + qv.z*kv2.z + qv.w*kv3.z;
                s_[i][3] += qv.x*kv0.w + qv.y*kv1.w + qv.z*kv2.w + qv.w*kv3.w;
            }
        }

        // Online softmax update (row stats reduced across the 16 tx lanes)
        #pragma unroll
        for (int i = 0; i < 4; i++) {
            float tmax = fmaxf(fmaxf(s_[i][0], s_[i][1]), fmaxf(s_[i][2], s_[i][3]));
            #pragma unroll
            for (int off = 8; off > 0; off >>= 1)
                tmax = fmaxf(tmax, __shfl_xor_sync(0xffffffffu, tmax, off, 16));
            float mnew  = fmaxf(m_i[i], tmax);
            float alpha = __expf(m_i[i] - mnew);
            m_i[i] = mnew;
            float p0 = __expf(s_[i][0] - mnew);
            float p1 = __expf(s_[i][1] - mnew);
            float p2 = __expf(s_[i][2] - mnew);
            float p3 = __expf(s_[i][3] - mnew);
            *(float4*)&ps[(r0 + i) * DPAD + c0] = make_float4(p0, p1, p2, p3);
            float psum = p0 + p1 + p2 + p3;
            #pragma unroll
            for (int off = 8; off > 0; off >>= 1)
                psum += __shfl_xor_sync(0xffffffffu, psum, off, 16);
            l_i[i] = l_i[i] * alpha + psum;
            acc[i][0] *= alpha; acc[i][1] *= alpha;
            acc[i][2] *= alpha; acc[i][3] *= alpha;
        }
        __syncthreads();

        // acc += P @ V
        for (int j4 = 0; j4 < TS; j4 += 4) {
            float4 v0 = *(const float4*)&vs[(j4 + 0) * DPAD + c0];
            float4 v1 = *(const float4*)&vs[(j4 + 1) * DPAD + c0];
            float4 v2 = *(const float4*)&vs[(j4 + 2) * DPAD + c0];
            float4 v3 = *(const float4*)&vs[(j4 + 3) * DPAD + c0];
            #pragma unroll
            for (int i = 0; i < 4; i++) {
                float4 pv = *(const float4*)&ps[(r0 + i) * DPAD + j4];
                acc[i][0] += pv.x*v0.x + pv.y*v1.x + pv.z*v2.x + pv.w*v3.x;
                acc[i][1] += pv.x*v0.y + pv.y*v1.y + pv.z*v2.y + pv.w*v3.y;
                acc[i][2] += pv.x*v0.z + pv.y*v1.z + pv.z*v2.z + pv.w*v3.z;
                acc[i][3] += pv.x*v0.w + pv.y*v1.w + pv.z*v2.w + pv.w*v3.w;
            }
        }
    }

    // Normalize and store (layout matches (b, t, H*HD) for the output GEMM)
    #pragma unroll
    for (int i = 0; i < 4; i++) {
        float inv = 1.0f / l_i[i];
        float4 vr = make_float4(acc[i][0]*inv, acc[i][1]*inv, acc[i][2]*inv, acc[i][3]*inv);
        *(float4*)&o[((b * T_ + t0 + r0 + i) * H_ + h) * HD_ + c0] = vr;
    }
}

// ---------------------------------------------------------------------------
extern "C" void kernel_launch(void* const* d_in, const int* in_sizes, int n_in,
                              void* d_out, int out_size) {
    const float* x    = (const float*)d_in[0];
    const float* y    = (const float*)d_in[1];
    const float* cosb = (const float*)d_in[2];
    const float* sinb = (const float*)d_in[3];
    const float* mask = (const float*)d_in[4];
    const float* Wq   = (const float*)d_in[5];
    const float* Wk   = (const float*)d_in[6];
    const float* Wv   = (const float*)d_in[7];
    const float* Wo   = (const float*)d_in[8];
    float* out = (float*)d_out;

    void *pq, *pk, *pv, *po;
    cudaGetSymbolAddress(&pq, g_q);
    cudaGetSymbolAddress(&pk, g_k);
    cudaGetSymbolAddress(&pv, g_v);
    cudaGetSymbolAddress(&po, g_o);

    const int M = B_ * T_;            // 4096
    dim3 ggrid(DM_ / BN, M / BM);     // (16, 32)

    sgemm_kernel<<<ggrid, 256>>>(x, Wq, (float*)pq, M, DM_, DM_);
    sgemm_kernel<<<ggrid, 256>>>(y, Wk, (float*)pk, M, DM_, DM_);
    sgemm_kernel<<<ggrid, 256>>>(y, Wv, (float*)pv, M, DM_, DM_);

    rope_kernel<<<4096, 256>>>((float*)pq, cosb, sinb);
    rope_kernel<<<4096, 256>>>((float*)pk, cosb, sinb);

    cudaFuncSetAttribute(flash_attn_kernel,
                         cudaFuncAttributeMaxDynamicSharedMemorySize, FA_SMEM);
    flash_attn_kernel<<<dim3(T_ / TQ, H_, B_), 256, FA_SMEM>>>(
        (const float*)pq, (const float*)pk, (const float*)pv, mask, (float*)po);

    sgemm_kernel<<<ggrid, 256>>>((const float*)po, Wo, out, M, DM_, DM_);
}

// round 2
// speedup vs baseline: 1.9277x; 1.9277x over previous
#include <cuda_runtime.h>

#define B_  2
#define T_  2048
#define S_  2048
#define H_  16
#define HD_ 64
#define DM_ 1024

// Scratch (allocation-free rule: __device__ globals)
__device__ float g_q[B_*T_*H_*HD_];
__device__ float g_k[B_*S_*H_*HD_];
__device__ float g_v[B_*S_*H_*HD_];
__device__ float g_o[B_*T_*H_*HD_];

// ---------------------------------------------------------------------------
// tf32 helpers
// ---------------------------------------------------------------------------
__device__ __forceinline__ unsigned f2tf(float f) {
    unsigned u;
    asm("cvt.rna.tf32.f32 %0, %1;" : "=r"(u) : "f"(f));
    return u;
}

__device__ __forceinline__ void mma8(float c[4], const unsigned a[4], const unsigned b[2]) {
    asm volatile(
        "mma.sync.aligned.m16n8k8.row.col.f32.tf32.tf32.f32 "
        "{%0,%1,%2,%3}, {%4,%5,%6,%7}, {%8,%9}, {%0,%1,%2,%3};"
        : "+f"(c[0]), "+f"(c[1]), "+f"(c[2]), "+f"(c[3])
        : "r"(a[0]), "r"(a[1]), "r"(a[2]), "r"(a[3]), "r"(b[0]), "r"(b[1]));
}

// ---------------------------------------------------------------------------
// tf32 tensor-core GEMM: C[M,N] = A[M,K] @ B[K,N], row-major fp32 in/out.
// 128x128x32 block tile, 256 threads (8 warps as 2x4), smem in fragment order,
// double buffered with register prefetch.
//
// A-frag smem: tiles (mt 0..7 of 16 rows) x (kt 0..3 of 8 cols), each 128
// floats in m16n8k8 A-fragment order: idx = lane*4 + reg.
// B-frag smem: tiles (kt 0..3) x (nt 0..15 of 8 cols): 64 floats each,
// idx = lane*2 + reg.
// ---------------------------------------------------------------------------
#define GSM_FLOATS 8192   // per buffer: 4096 A-frag + 4096 B-frag
#define GEMM_SMEM (2 * GSM_FLOATS * 4)

__global__ __launch_bounds__(256)
void gemm_tf32(const float* __restrict__ A, const float* __restrict__ Bm,
               float* __restrict__ C, int M, int N, int K) {
    extern __shared__ float smg[];
    const int tid   = threadIdx.x;
    const int lane  = tid & 31;
    const int wid   = tid >> 5;
    const int warp_m = wid >> 2;      // 0..1
    const int warp_n = wid & 3;       // 0..3
    const int g    = lane >> 2;
    const int tig  = lane & 3;
    const int bm = blockIdx.y * 128;
    const int bn = blockIdx.x * 128;

    float acc[4][4][4];
    #pragma unroll
    for (int i = 0; i < 4; i++)
        #pragma unroll
        for (int j = 0; j < 4; j++)
            #pragma unroll
            for (int r = 0; r < 4; r++) acc[i][j][r] = 0.f;

    // global-load thread mapping
    const int arow  = tid >> 1;              // 0..127
    const int acb   = (tid & 1) * 16;        // col base (of 32)
    const int brow  = tid >> 3;              // 0..31
    const int bnb   = (tid & 7) * 16;        // col base (of 128)

    // A-scatter constants
    const int a_mt = arow >> 4;
    const int a_g  = arow & 7;
    const int a_r1 = (arow >> 3) & 1;
    // B-scatter constants
    const int b_kt  = brow >> 3;
    const int b_tig = brow & 3;
    const int b_rb  = (brow >> 2) & 1;

    float4 ra[4], rb[4];

    // prologue: load k-block 0
    #pragma unroll
    for (int i = 0; i < 4; i++)
        ra[i] = *(const float4*)&A[(size_t)(bm + arow) * K + acb + i * 4];
    #pragma unroll
    for (int i = 0; i < 4; i++)
        rb[i] = *(const float4*)&Bm[(size_t)brow * N + bn + bnb + i * 4];

    // scatter k-block 0 into buffer 0
    {
        float* af = smg;
        float* bf = smg + 4096;
        #pragma unroll
        for (int i = 0; i < 4; i++) {
            float vv[4] = {ra[i].x, ra[i].y, ra[i].z, ra[i].w};
            #pragma unroll
            for (int j = 0; j < 4; j++) {
                int c = acb + i * 4 + j;
                int kt = c >> 3, ctig = c & 3, hi = (c >> 2) & 1;
                af[((a_mt * 4 + kt) << 7) + ((a_g * 4 + ctig) << 2) + a_r1 + 2 * hi] =
                    __uint_as_float(f2tf(vv[j]));
            }
        }
        #pragma unroll
        for (int i = 0; i < 4; i++) {
            float vv[4] = {rb[i].x, rb[i].y, rb[i].z, rb[i].w};
            #pragma unroll
            for (int j = 0; j < 4; j++) {
                int n = bnb + i * 4 + j;
                int nt = n >> 3, bg = n & 7;
                bf[((b_kt * 16 + nt) << 6) + ((bg * 4 + b_tig) << 1) + b_rb] =
                    __uint_as_float(f2tf(vv[j]));
            }
        }
    }

    const int nk = K >> 5;
    int s = 0;
    for (int kb = 0; kb < nk; kb++) {
        __syncthreads();
        // prefetch next k-block into registers
        if (kb + 1 < nk) {
            #pragma unroll
            for (int i = 0; i < 4; i++)
                ra[i] = *(const float4*)&A[(size_t)(bm + arow) * K + (kb + 1) * 32 + acb + i * 4];
            #pragma unroll
            for (int i = 0; i < 4; i++)
                rb[i] = *(const float4*)&Bm[(size_t)((kb + 1) * 32 + brow) * N + bn + bnb + i * 4];
        }
        // compute from buffer s
        const float* af = smg + s * GSM_FLOATS;
        const float* bf = af + 4096;
        #pragma unroll
        for (int kt = 0; kt < 4; kt++) {
            unsigned a[4][4], b[4][2];
            #pragma unroll
            for (int im = 0; im < 4; im++)
                *(uint4*)a[im] = *(const uint4*)&af[(((warp_m * 4 + im) * 4 + kt) << 7) + lane * 4];
            #pragma unroll
            for (int in_ = 0; in_ < 4; in_++)
                *(uint2*)b[in_] = *(const uint2*)&bf[((kt * 16 + warp_n * 4 + in_) << 6) + lane * 2];
            #pragma unroll
            for (int im = 0; im < 4; im++)
                #pragma unroll
                for (int in_ = 0; in_ < 4; in_++)
                    mma8(acc[im][in_], a[im], b[in_]);
        }
        // scatter prefetched regs into the other buffer
        if (kb + 1 < nk) {
            float* af2 = smg + (s ^ 1) * GSM_FLOATS;
            float* bf2 = af2 + 4096;
            #pragma unroll
            for (int i = 0; i < 4; i++) {
                float vv[4] = {ra[i].x, ra[i].y, ra[i].z, ra[i].w};
                #pragma unroll
                for (int j = 0; j < 4; j++) {
                    int c = acb + i * 4 + j;
                    int kt = c >> 3, ctig = c & 3, hi = (c >> 2) & 1;
                    af2[((a_mt * 4 + kt) << 7) + ((a_g * 4 + ctig) << 2) + a_r1 + 2 * hi] =
                        __uint_as_float(f2tf(vv[j]));
                }
            }
            #pragma unroll
            for (int i = 0; i < 4; i++) {
                float vv[4] = {rb[i].x, rb[i].y, rb[i].z, rb[i].w};
                #pragma unroll
                for (int j = 0; j < 4; j++) {
                    int n = bnb + i * 4 + j;
                    int nt = n >> 3, bg = n & 7;
                    bf2[((b_kt * 16 + nt) << 6) + ((bg * 4 + b_tig) << 1) + b_rb] =
                        __uint_as_float(f2tf(vv[j]));
                }
            }
        }
        s ^= 1;
    }

    // epilogue
    #pragma unroll
    for (int im = 0; im < 4; im++) {
        int r0 = bm + warp_m * 64 + im * 16 + g;
        #pragma unroll
        for (int in_ = 0; in_ < 4; in_++) {
            int cc = bn + warp_n * 32 + in_ * 8 + tig * 2;
            *(float2*)&C[(size_t)r0 * N + cc]       = make_float2(acc[im][in_][0], acc[im][in_][1]);
            *(float2*)&C[(size_t)(r0 + 8) * N + cc] = make_float2(acc[im][in_][2], acc[im][in_][3]);
        }
    }
}

// ---------------------------------------------------------------------------
// Partial RoPE (unchanged): first 32 dims, rotate-half with half=16.
// ---------------------------------------------------------------------------
__global__ void rope_kernel(float* __restrict__ t,
                            const float* __restrict__ cosb,
                            const float* __restrict__ sinb) {
    int idx = blockIdx.x * blockDim.x + threadIdx.x;
    int d   = idx & 15;
    int h   = (idx >> 4) & (H_ - 1);
    int pos = (idx >> 8) & (T_ - 1);
    int b   = idx >> 19;
    float* base = t + ((size_t)(b * T_ + pos) * H_ + h) * HD_;
    float c = cosb[pos * 16 + d];
    float s = sinb[pos * 16 + d];
    float x1 = base[d];
    float x2 = base[d + 16];
    base[d]      = x1 * c - x2 * s;
    base[d + 16] = x2 * c + x1 * s;
}

// ---------------------------------------------------------------------------
// Fused flash attention, tf32 tensor cores.
// CTA = 128 q rows x one (b,h). 8 warps; warp owns 16 q rows x full 64-key
// tile, so online softmax is warp-local. K tile iterated over S in steps
// of 64.
// smem: qf (Q A-frags, 8192f) | kf (K B-frags, 4096f) | vf (V B-frags, 4096f)
//     | pf (P A-frags, warp-private, 8192f)
// ---------------------------------------------------------------------------
#define AT_SMEM (24576 * 4)

__global__ __launch_bounds__(256, 2)
void attn_tf32(const float* __restrict__ q, const float* __restrict__ k,
               const float* __restrict__ v, const float* __restrict__ mask,
               float* __restrict__ o) {
    extern __shared__ float sma[];
    float* qf = sma;            // 8192
    float* kf = sma + 8192;     // 4096
    float* vf = sma + 12288;    // 4096
    float* pf = sma + 16384;    // 8192

    const int tid  = threadIdx.x;
    const int lane = tid & 31;
    const int wid  = tid >> 5;
    const int g    = lane >> 2;
    const int tig  = lane & 3;
    const int t0   = blockIdx.x * 128;
    const int h    = blockIdx.y;
    const int b    = blockIdx.z;

    // ---- load Q tile (128x64) into A-frag order, scale by 1/sqrt(64) ----
    {
        int row = tid >> 1;
        const float* qrow = &q[(((size_t)b * T_ + t0 + row) * H_ + h) * HD_];
        int mt = row >> 4, rr = row & 15, qg = rr & 7, r1 = rr >> 3;
        #pragma unroll
        for (int i = 0; i < 8; i++) {
            int d0 = (tid & 1) * 32 + i * 4;
            float4 vq = *(const float4*)&qrow[d0];
            float vv[4] = {vq.x, vq.y, vq.z, vq.w};
            #pragma unroll
            for (int j = 0; j < 4; j++) {
                int d = d0 + j;
                int kt = d >> 3, dtig = d & 3, hi = (d >> 2) & 1;
                qf[((mt * 8 + kt) << 7) + ((qg * 4 + dtig) << 2) + r1 + 2 * hi] =
                    __uint_as_float(f2tf(vv[j] * 0.125f));
            }
        }
    }

    float m_[2] = {-1e30f, -1e30f};
    float l_[2] = {0.f, 0.f};
    float acc[8][4];
    #pragma unroll
    for (int nt = 0; nt < 8; nt++)
        #pragma unroll
        for (int r = 0; r < 4; r++) acc[nt][r] = 0.f;

    const int krow = tid >> 2;          // 0..63 (key/value row within tile)
    const int kcb  = (tid & 3) * 16;    // d base

    // K-scatter constants (n dim = s)
    const int kn_nt = krow >> 3, kn_g = krow & 7;
    // V-scatter constants (k dim = s)
    const int vk_kt = krow >> 3, vk_tig = krow & 3, vk_rb = (krow >> 2) & 1;

    for (int s0 = 0; s0 < S_; s0 += 64) {
        __syncthreads();
        // ---- load K and V tiles (64x64 each) into B-frag order ----
        {
            const float* kr = &k[(((size_t)b * S_ + s0 + krow) * H_ + h) * HD_];
            const float* vr = &v[(((size_t)b * S_ + s0 + krow) * H_ + h) * HD_];
            #pragma unroll
            for (int i = 0; i < 4; i++) {
                int d0 = kcb + i * 4;
                float4 kv = *(const float4*)&kr[d0];
                float4 vv4 = *(const float4*)&vr[d0];
                float kvv[4] = {kv.x, kv.y, kv.z, kv.w};
                float vvv[4] = {vv4.x, vv4.y, vv4.z, vv4.w};
                #pragma unroll
                for (int j = 0; j < 4; j++) {
                    int d = d0 + j;
                    int kkt = d >> 3, ktig = d & 3, krb = (d >> 2) & 1;
                    kf[((kkt * 8 + kn_nt) << 6) + ((kn_g * 4 + ktig) << 1) + krb] =
                        __uint_as_float(f2tf(kvv[j]));
                    int vnt = d >> 3, vg = d & 7;
                    vf[((vk_kt * 8 + vnt) << 6) + ((vg * 4 + vk_tig) << 1) + vk_rb] =
                        __uint_as_float(f2tf(vvv[j]));
                }
            }
        }
        __syncthreads();

        // ---- scores = mask ----
        float sc[8][4];
        {
            const float* mr0 = &mask[((size_t)b * T_ + t0 + wid * 16 + g) * S_ + s0];
            const float* mr1 = mr0 + 8 * S_;
            #pragma unroll
            for (int nt = 0; nt < 8; nt++) {
                float2 m0 = *(const float2*)&mr0[nt * 8 + 2 * tig];
                float2 m1 = *(const float2*)&mr1[nt * 8 + 2 * tig];
                sc[nt][0] = m0.x; sc[nt][1] = m0.y;
                sc[nt][2] = m1.x; sc[nt][3] = m1.y;
            }
        }
        // ---- scores += Q @ K^T ----
        #pragma unroll
        for (int kt = 0; kt < 8; kt++) {
            unsigned a[4];
            *(uint4*)a = *(const uint4*)&qf[((wid * 8 + kt) << 7) + lane * 4];
            #pragma unroll
            for (int nt = 0; nt < 8; nt++) {
                unsigned bb[2];
                *(uint2*)bb = *(const uint2*)&kf[((kt * 8 + nt) << 6) + lane * 2];
                mma8(sc[nt], a, bb);
            }
        }

        // ---- online softmax (warp-local; rows g and g+8) ----
        #pragma unroll
        for (int e = 0; e < 2; e++) {
            float tmax = -1e30f;
            #pragma unroll
            for (int nt = 0; nt < 8; nt++)
                tmax = fmaxf(tmax, fmaxf(sc[nt][2 * e], sc[nt][2 * e + 1]));
            tmax = fmaxf(tmax, __shfl_xor_sync(0xffffffffu, tmax, 1));
            tmax = fmaxf(tmax, __shfl_xor_sync(0xffffffffu, tmax, 2));
            float mnew  = fmaxf(m_[e], tmax);
            float alpha = __expf(m_[e] - mnew);
            m_[e] = mnew;
            float ps = 0.f;
            #pragma unroll
            for (int nt = 0; nt < 8; nt++) {
                float p0 = __expf(sc[nt][2 * e]     - mnew);
                float p1 = __expf(sc[nt][2 * e + 1] - mnew);
                sc[nt][2 * e] = p0; sc[nt][2 * e + 1] = p1;
                ps += p0 + p1;
            }
            ps += __shfl_xor_sync(0xffffffffu, ps, 1);
            ps += __shfl_xor_sync(0xffffffffu, ps, 2);
            l_[e] = l_[e] * alpha + ps;
            #pragma unroll
            for (int nt = 0; nt < 8; nt++) {
                acc[nt][2 * e]     *= alpha;
                acc[nt][2 * e + 1] *= alpha;
            }
        }

        // ---- store P into warp-private A-frag region ----
        float* pw = pf + wid * 1024;
        #pragma unroll
        for (int nt = 0; nt < 8; nt++) {
            #pragma unroll
            for (int r1 = 0; r1 < 2; r1++) {
                #pragma unroll
                for (int e = 0; e < 2; e++) {
                    int c = 2 * tig + e;
                    pw[(nt << 7) + ((g * 4 + (c & 3)) << 2) + r1 + 2 * (tig >> 1)] =
                        __uint_as_float(f2tf(sc[nt][r1 * 2 + e]));
                }
            }
        }
        __syncwarp();

        // ---- acc += P @ V ----
        #pragma unroll
        for (int kt = 0; kt < 8; kt++) {
            unsigned a[4];
            *(uint4*)a = *(const uint4*)&pw[(kt << 7) + lane * 4];
            #pragma unroll
            for (int nt = 0; nt < 8; nt++) {
                unsigned bb[2];
                *(uint2*)bb = *(const uint2*)&vf[((kt * 8 + nt) << 6) + lane * 2];
                mma8(acc[nt], a, bb);
            }
        }
    }

    // ---- normalize + store ----
    float inv0 = 1.f / l_[0];
    float inv1 = 1.f / l_[1];
    float* o0 = &o[(((size_t)b * T_ + t0 + wid * 16 + g) * H_ + h) * HD_];
    float* o1 = o0 + (size_t)8 * H_ * HD_;
    #pragma unroll
    for (int nt = 0; nt < 8; nt++) {
        *(float2*)&o0[nt * 8 + 2 * tig] = make_float2(acc[nt][0] * inv0, acc[nt][1] * inv0);
        *(float2*)&o1[nt * 8 + 2 * tig] = make_float2(acc[nt][2] * inv1, acc[nt][3] * inv1);
    }
}

// ---------------------------------------------------------------------------
extern "C" void kernel_launch(void* const* d_in, const int* in_sizes, int n_in,
                              void* d_out, int out_size) {
    const float* x    = (const float*)d_in[0];
    const float* y    = (const float*)d_in[1];
    const float* cosb = (const float*)d_in[2];
    const float* sinb = (const float*)d_in[3];
    const float* mask = (const float*)d_in[4];
    const float* Wq   = (const float*)d_in[5];
    const float* Wk   = (const float*)d_in[6];
    const float* Wv   = (const float*)d_in[7];
    const float* Wo   = (const float*)d_in[8];
    float* out = (float*)d_out;

    void *pq, *pk, *pv, *po;
    cudaGetSymbolAddress(&pq, g_q);
    cudaGetSymbolAddress(&pk, g_k);
    cudaGetSymbolAddress(&pv, g_v);
    cudaGetSymbolAddress(&po, g_o);

    cudaFuncSetAttribute(gemm_tf32, cudaFuncAttributeMaxDynamicSharedMemorySize, GEMM_SMEM);
    cudaFuncSetAttribute(attn_tf32, cudaFuncAttributeMaxDynamicSharedMemorySize, AT_SMEM);

    const int M = B_ * T_;                 // 4096
    dim3 ggrid(DM_ / 128, M / 128);        // (8, 32)

    gemm_tf32<<<ggrid, 256, GEMM_SMEM>>>(x, Wq, (float*)pq, M, DM_, DM_);
    gemm_tf32<<<ggrid, 256, GEMM_SMEM>>>(y, Wk, (float*)pk, M, DM_, DM_);
    gemm_tf32<<<ggrid, 256, GEMM_SMEM>>>(y, Wv, (float*)pv, M, DM_, DM_);

    rope_kernel<<<4096, 256>>>((float*)pq, cosb, sinb);
    rope_kernel<<<4096, 256>>>((float*)pk, cosb, sinb);

    attn_tf32<<<dim3(T_ / 128, H_, B_), 256, AT_SMEM>>>(
        (const float*)pq, (const float*)pk, (const float*)pv, mask, (float*)po);

    gemm_tf32<<<ggrid, 256, GEMM_SMEM>>>((const float*)po, Wo, out, M, DM_, DM_);
}

// round 4
// speedup vs baseline: 4.0679x; 2.1103x over previous
#include <cuda_runtime.h>
#include <cuda_fp16.h>
#include <cstdint>

#define B_  2
#define T_  2048
#define S_  2048
#define H_  16
#define HD_ 64
#define DM_ 1024

// Scratch (allocation-free rule: __device__ globals)
__device__ float g_q[B_*T_*H_*HD_];
__device__ float g_k[B_*S_*H_*HD_];
__device__ float g_v[B_*S_*H_*HD_];
__device__ float g_o[B_*T_*H_*HD_];
// fp16 fragment-order operands
__device__ unsigned g_xA[B_*T_*DM_/2];
__device__ unsigned g_yA[B_*S_*DM_/2];
__device__ unsigned g_oA[B_*T_*DM_/2];
__device__ unsigned g_WqB[DM_*DM_/2];
__device__ unsigned g_WkB[DM_*DM_/2];
__device__ unsigned g_WvB[DM_*DM_/2];
__device__ unsigned g_WoB[DM_*DM_/2];

// ---------------------------------------------------------------------------
// helpers
// ---------------------------------------------------------------------------
__device__ __forceinline__ unsigned packh2(float a, float b) {
    __half2 h = __floats2half2_rn(a, b);
    return *(unsigned*)&h;
}

__device__ __forceinline__ void mma16(float c[4], const unsigned a[4], const unsigned b[2]) {
    asm volatile(
        "mma.sync.aligned.m16n8k16.row.col.f32.f16.f16.f32 "
        "{%0,%1,%2,%3}, {%4,%5,%6,%7}, {%8,%9}, {%0,%1,%2,%3};"
        : "+f"(c[0]), "+f"(c[1]), "+f"(c[2]), "+f"(c[3])
        : "r"(a[0]), "r"(a[1]), "r"(a[2]), "r"(a[3]), "r"(b[0]), "r"(b[1]));
}

__device__ __forceinline__ uint32_t smem_u32(const void* p) {
    uint32_t a;
    asm("{ .reg .u64 t; cvta.to.shared.u64 t, %1; cvt.u32.u64 %0, t; }" : "=r"(a) : "l"(p));
    return a;
}

#define CP_ASYNC16(dst, src) \
    asm volatile("cp.async.cg.shared.global [%0], [%1], 16;" :: "r"(dst), "l"(src) : "memory")
#define CP_COMMIT() asm volatile("cp.async.commit_group;" ::: "memory")
#define CP_WAIT1()  asm volatile("cp.async.wait_group 1;" ::: "memory")
#define CP_WAIT0()  asm volatile("cp.async.wait_group 0;" ::: "memory")

// ---------------------------------------------------------------------------
// Conversion: fp32 row-major [M x 1024] -> fp16 A-fragment order.
// Tile (mt = row>>4, kt = col>>4), 128 u32/tile: word = lane*4 + reg,
// lane = (rowin&7)*4 + ((colin>>1)&3), reg = (rowin>>3) + 2*(colin>>3).
// ---------------------------------------------------------------------------
__global__ __launch_bounds__(256)
void convA1024(const float* __restrict__ src, unsigned* __restrict__ dst) {
    size_t idx = (size_t)blockIdx.x * 256 + threadIdx.x;   // M*512
    int row = (int)(idx >> 9);
    int c   = (int)(idx & 511) << 1;
    float2 v = *(const float2*)&src[(size_t)row * 1024 + c];
    int mt = row >> 4, rr = row & 15, g = rr & 7, hr = rr >> 3;
    int kt = c >> 4, cc = c & 15, tig = (cc >> 1) & 3, hc = cc >> 3;
    dst[((size_t)(mt * 64 + kt) << 7) + ((g * 4 + tig) << 2) + hr + 2 * hc] =
        packh2(v.x, v.y);
}

// ---------------------------------------------------------------------------
// Conversion: W fp32 [1024 x 1024] row-major -> fp16 B-fragment order (col dim n).
// Tile (kt = k>>4, nt = n>>3), 64 u32/tile: word = lane*2 + hi,
// lane = (n&7)*4 + ((kin&7)>>1), hi = kin>>3, halves = k parity (even = low).
// ---------------------------------------------------------------------------
__global__ __launch_bounds__(256)
void convB1024(const float* __restrict__ W, unsigned* __restrict__ dst) {
    size_t idx = (size_t)blockIdx.x * 256 + threadIdx.x;   // 512*1024
    int n = (int)(idx & 1023);
    int k = (int)(idx >> 10) << 1;
    float lo = W[(size_t)k * 1024 + n];
    float hi = W[(size_t)(k + 1) * 1024 + n];
    int kt = k >> 4, kk = k & 15, hb = kk >> 3, tig = (kk & 7) >> 1;
    int nt = n >> 3, g = n & 7;
    dst[((size_t)(kt * 128 + nt) << 6) + ((g * 4 + tig) << 1) + hb] = packh2(lo, hi);
}

// ---------------------------------------------------------------------------
// fp16 tensor-core GEMM from pre-fragmented operands.
// C[M,N] = A[M,K] @ W[K,N], fp32 out. 128x128x32 tile, 256 thr (8 warps 2x4),
// 3-stage cp.async pipeline. smem/buffer: A 2048 u32 + B 2048 u32.
// ---------------------------------------------------------------------------
#define GT_SMEM 49152

__global__ __launch_bounds__(256)
void gemm_f16(const uint4* __restrict__ Af, const uint4* __restrict__ Bf,
              float* __restrict__ C, int M, int N, int K) {
    extern __shared__ unsigned sm16[];
    const uint32_t sb = smem_u32(sm16);
    const int tid  = threadIdx.x;
    const int lane = tid & 31;
    const int wid  = tid >> 5;
    const int warp_m = wid >> 2;
    const int warp_n = wid & 3;
    const int g   = lane >> 2;
    const int tig = lane & 3;
    const int bm = blockIdx.y * 128;
    const int bn = blockIdx.x * 128;
    const int ktiles = K >> 4;
    const int ntiles = N >> 3;
    const int nkb = K >> 5;

    float acc[4][4][4];
    #pragma unroll
    for (int i = 0; i < 4; i++)
        #pragma unroll
        for (int j = 0; j < 4; j++)
            #pragma unroll
            for (int r = 0; r < 4; r++) acc[i][j][r] = 0.f;

    // issue one chunk's loads into buffer `buf`
    auto issue = [&](int kb, int buf) {
        #pragma unroll
        for (int u = 0; u < 2; u++) {
            int i = tid + u * 256;
            // A: 512 uint4s, tile = i>>5 (mt*2+kt)
            int ti = i >> 5, mt = ti >> 1, kt = ti & 1;
            size_t gt = (size_t)((bm >> 4) + mt) * ktiles + kb * 2 + kt;
            CP_ASYNC16(sb + (buf * 4096 + ti * 128 + (i & 31) * 4) * 4,
                       Af + gt * 32 + (i & 31));
            // B: 512 uint4s, tile = i>>4 (kt*16+nt)
            int tj = i >> 4, bkt = tj >> 4, nt = tj & 15;
            size_t gtb = (size_t)(kb * 2 + bkt) * ntiles + (bn >> 3) + nt;
            CP_ASYNC16(sb + (buf * 4096 + 2048 + tj * 64 + (i & 15) * 4) * 4,
                       Bf + gtb * 16 + (i & 15));
        }
        CP_COMMIT();
    };

    issue(0, 0);
    issue(1, 1);

    for (int kb = 0; kb < nkb; kb++) {
        if (kb + 2 < nkb) { CP_WAIT1(); } else { CP_WAIT0(); }
        __syncthreads();
        if (kb + 2 < nkb) issue(kb + 2, (kb + 2) % 3);

        const int buf = kb % 3;
        const unsigned* aw = sm16 + buf * 4096;
        const unsigned* bw = aw + 2048;
        #pragma unroll
        for (int kt = 0; kt < 2; kt++) {
            unsigned a[4][4], b[4][2];
            #pragma unroll
            for (int im = 0; im < 4; im++)
                *(uint4*)a[im] = *(const uint4*)&aw[(((warp_m * 4 + im) * 2 + kt) << 7) + lane * 4];
            #pragma unroll
            for (int in_ = 0; in_ < 4; in_++)
                *(uint2*)b[in_] = *(const uint2*)&bw[((kt * 16 + warp_n * 4 + in_) << 6) + lane * 2];
            #pragma unroll
            for (int im = 0; im < 4; im++)
                #pragma unroll
                for (int in_ = 0; in_ < 4; in_++)
                    mma16(acc[im][in_], a[im], b[in_]);
        }
        __syncthreads();
    }

    #pragma unroll
    for (int im = 0; im < 4; im++) {
        int r0 = bm + warp_m * 64 + im * 16 + g;
        #pragma unroll
        for (int in_ = 0; in_ < 4; in_++) {
            int cc = bn + warp_n * 32 + in_ * 8 + tig * 2;
            *(float2*)&C[(size_t)r0 * N + cc]       = make_float2(acc[im][in_][0], acc[im][in_][1]);
            *(float2*)&C[(size_t)(r0 + 8) * N + cc] = make_float2(acc[im][in_][2], acc[im][in_][3]);
        }
    }
}

// ---------------------------------------------------------------------------
// Partial RoPE (unchanged)
// ---------------------------------------------------------------------------
__global__ void rope_kernel(float* __restrict__ t,
                            const float* __restrict__ cosb,
                            const float* __restrict__ sinb) {
    int idx = blockIdx.x * blockDim.x + threadIdx.x;
    int d   = idx & 15;
    int h   = (idx >> 4) & (H_ - 1);
    int pos = (idx >> 8) & (T_ - 1);
    int b   = idx >> 19;
    float* base = t + ((size_t)(b * T_ + pos) * H_ + h) * HD_;
    float c = cosb[pos * 16 + d];
    float s = sinb[pos * 16 + d];
    float x1 = base[d];
    float x2 = base[d + 16];
    base[d]      = x1 * c - x2 * s;
    base[d + 16] = x2 * c + x1 * s;
}

// ---------------------------------------------------------------------------
// Fused flash attention, fp16 mma.sync m16n8k16.
// CTA = 128 q rows x one (b,h); warp owns 16 q rows; warp-local softmax.
// smem u32 map: qf [0,4096) | kf [4096,6144) | vf [6144,8192) | pf [8192,12288)
// ---------------------------------------------------------------------------
#define AT_SMEM 49152

__global__ __launch_bounds__(256, 2)
void attn_f16(const float* __restrict__ q, const float* __restrict__ k,
              const float* __restrict__ v, const float* __restrict__ mask,
              float* __restrict__ o) {
    extern __shared__ unsigned sma[];
    unsigned* qf = sma;
    unsigned* kf = sma + 4096;
    unsigned* vf = sma + 6144;
    unsigned* pf = sma + 8192;

    const int tid  = threadIdx.x;
    const int lane = tid & 31;
    const int wid  = tid >> 5;
    const int g    = lane >> 2;
    const int tig  = lane & 3;
    const int t0   = blockIdx.x * 128;
    const int h    = blockIdx.y;
    const int b    = blockIdx.z;

    // ---- Q (128x64) -> A-frag order, scaled by 0.125 ----
    {
        int row = tid >> 1;
        const float* qrow = &q[(((size_t)b * T_ + t0 + row) * H_ + h) * HD_];
        int mt = row >> 4, rr = row & 15, qg = rr & 7, hr = rr >> 3;
        #pragma unroll
        for (int i = 0; i < 8; i++) {
            int c4 = (tid & 1) * 32 + i * 4;
            float4 vq = *(const float4*)&qrow[c4];
            int kt = c4 >> 4, cc = c4 & 15;
            int tg0 = (cc >> 1) & 3, hc0 = cc >> 3;
            int cc2 = cc + 2;
            int tg1 = (cc2 >> 1) & 3, hc1 = cc2 >> 3;
            qf[((mt * 4 + kt) << 7) + ((qg * 4 + tg0) << 2) + hr + 2 * hc0] =
                packh2(vq.x * 0.125f, vq.y * 0.125f);
            qf[((mt * 4 + kt) << 7) + ((qg * 4 + tg1) << 2) + hr + 2 * hc1] =
                packh2(vq.z * 0.125f, vq.w * 0.125f);
        }
    }

    float m_[2] = {-1e30f, -1e30f};
    float l_[2] = {0.f, 0.f};
    float acc[8][4];
    #pragma unroll
    for (int nt = 0; nt < 8; nt++)
        #pragma unroll
        for (int r = 0; r < 4; r++) acc[nt][r] = 0.f;

    const int krow = tid >> 2;          // 0..63
    const int kcb  = (tid & 3) * 16;
    const int kg  = krow & 7, knt = krow >> 3;                       // K: n = s
    const int vkt = krow >> 4, vkk = krow & 15;                      // V: k = s
    const int vhi = vkk >> 3, vtig = (vkk & 7) >> 1, vlo = vkk & 1;
    __half* vfh = (__half*)vf;

    for (int s0 = 0; s0 < S_; s0 += 64) {
        __syncthreads();
        // ---- K, V tiles (64x64) -> B-frag order ----
        {
            const float* kr = &k[(((size_t)b * S_ + s0 + krow) * H_ + h) * HD_];
            const float* vr = &v[(((size_t)b * S_ + s0 + krow) * H_ + h) * HD_];
            #pragma unroll
            for (int i = 0; i < 4; i++) {
                int d0 = kcb + i * 4;
                float4 kv = *(const float4*)&kr[d0];
                float4 vv = *(const float4*)&vr[d0];
                // K: pairs along d (k-dim)
                int kkt = d0 >> 4, kkk = d0 & 15;
                int kh0 = kkk >> 3, kt0 = (kkk & 7) >> 1;
                int kkk2 = kkk + 2;
                int kh1 = kkk2 >> 3, kt1 = (kkk2 & 7) >> 1;
                kf[((kkt * 8 + knt) << 6) + ((kg * 4 + kt0) << 1) + kh0] = packh2(kv.x, kv.y);
                kf[((kkt * 8 + knt) << 6) + ((kg * 4 + kt1) << 1) + kh1] = packh2(kv.z, kv.w);
                // V: d is n-dim, s parity selects half
                float vvv[4] = {vv.x, vv.y, vv.z, vv.w};
                #pragma unroll
                for (int j = 0; j < 4; j++) {
                    int d = d0 + j;
                    int vg = d & 7, vnt = d >> 3;
                    int word = ((vkt * 8 + vnt) << 6) + ((vg * 4 + vtig) << 1) + vhi;
                    vfh[word * 2 + vlo] = __float2half_rn(vvv[j]);
                }
            }
        }
        __syncthreads();

        // ---- scores = mask ----
        float sc[8][4];
        {
            const float* mr0 = &mask[((size_t)b * T_ + t0 + wid * 16 + g) * S_ + s0];
            const float* mr1 = mr0 + 8 * S_;
            #pragma unroll
            for (int nt = 0; nt < 8; nt++) {
                float2 m0 = *(const float2*)&mr0[nt * 8 + 2 * tig];
                float2 m1 = *(const float2*)&mr1[nt * 8 + 2 * tig];
                sc[nt][0] = m0.x; sc[nt][1] = m0.y;
                sc[nt][2] = m1.x; sc[nt][3] = m1.y;
            }
        }
        // ---- scores += Q @ K^T ----
        #pragma unroll
        for (int kt = 0; kt < 4; kt++) {
            unsigned a[4];
            *(uint4*)a = *(const uint4*)&qf[((wid * 4 + kt) << 7) + lane * 4];
            #pragma unroll
            for (int nt = 0; nt < 8; nt++) {
                unsigned bb[2];
                *(uint2*)bb = *(const uint2*)&kf[((kt * 8 + nt) << 6) + lane * 2];
                mma16(sc[nt], a, bb);
            }
        }

        // ---- online softmax (warp-local) ----
        #pragma unroll
        for (int e = 0; e < 2; e++) {
            float tmax = -1e30f;
            #pragma unroll
            for (int nt = 0; nt < 8; nt++)
                tmax = fmaxf(tmax, fmaxf(sc[nt][2 * e], sc[nt][2 * e + 1]));
            tmax = fmaxf(tmax, __shfl_xor_sync(0xffffffffu, tmax, 1));
            tmax = fmaxf(tmax, __shfl_xor_sync(0xffffffffu, tmax, 2));
            float mnew  = fmaxf(m_[e], tmax);
            float alpha = __expf(m_[e] - mnew);
            m_[e] = mnew;
            float ps = 0.f;
            #pragma unroll
            for (int nt = 0; nt < 8; nt++) {
                float p0 = __expf(sc[nt][2 * e]     - mnew);
                float p1 = __expf(sc[nt][2 * e + 1] - mnew);
                sc[nt][2 * e] = p0; sc[nt][2 * e + 1] = p1;
                ps += p0 + p1;
            }
            ps += __shfl_xor_sync(0xffffffffu, ps, 1);
            ps += __shfl_xor_sync(0xffffffffu, ps, 2);
            l_[e] = l_[e] * alpha + ps;
            #pragma unroll
            for (int nt = 0; nt < 8; nt++) {
                acc[nt][2 * e]     *= alpha;
                acc[nt][2 * e + 1] *= alpha;
            }
        }

        // ---- P -> warp-private A-frags (own-lane u32 stores) ----
        unsigned* pw = pf + wid * 512;
        #pragma unroll
        for (int nt = 0; nt < 8; nt++) {
            #pragma unroll
            for (int hr = 0; hr < 2; hr++) {
                pw[((nt >> 1) << 7) + lane * 4 + hr + 2 * (nt & 1)] =
                    packh2(sc[nt][2 * hr], sc[nt][2 * hr + 1]);
            }
        }
        __syncwarp();

        // ---- acc += P @ V ----
        #pragma unroll
        for (int kt = 0; kt < 4; kt++) {
            unsigned a[4];
            *(uint4*)a = *(const uint4*)&pw[(kt << 7) + lane * 4];
            #pragma unroll
            for (int nt = 0; nt < 8; nt++) {
                unsigned bb[2];
                *(uint2*)bb = *(const uint2*)&vf[((kt * 8 + nt) << 6) + lane * 2];
                mma16(acc[nt], a, bb);
            }
        }
    }

    // ---- normalize + store ----
    float inv0 = 1.f / l_[0];
    float inv1 = 1.f / l_[1];
    float* o0 = &o[(((size_t)b * T_ + t0 + wid * 16 + g) * H_ + h) * HD_];
    float* o1 = o0 + (size_t)8 * H_ * HD_;
    #pragma unroll
    for (int nt = 0; nt < 8; nt++) {
        *(float2*)&o0[nt * 8 + 2 * tig] = make_float2(acc[nt][0] * inv0, acc[nt][1] * inv0);
        *(float2*)&o1[nt * 8 + 2 * tig] = make_float2(acc[nt][2] * inv1, acc[nt][3] * inv1);
    }
}

// ---------------------------------------------------------------------------
extern "C" void kernel_launch(void* const* d_in, const int* in_sizes, int n_in,
                              void* d_out, int out_size) {
    const float* x    = (const float*)d_in[0];
    const float* y    = (const float*)d_in[1];
    const float* cosb = (const float*)d_in[2];
    const float* sinb = (const float*)d_in[3];
    const float* mask = (const float*)d_in[4];
    const float* Wq   = (const float*)d_in[5];
    const float* Wk   = (const float*)d_in[6];
    const float* Wv   = (const float*)d_in[7];
    const float* Wo   = (const float*)d_in[8];
    float* out = (float*)d_out;

    void *pq, *pk, *pv, *po, *pxA, *pyA, *poA, *pWq, *pWk, *pWv, *pWo;
    cudaGetSymbolAddress(&pq, g_q);
    cudaGetSymbolAddress(&pk, g_k);
    cudaGetSymbolAddress(&pv, g_v);
    cudaGetSymbolAddress(&po, g_o);
    cudaGetSymbolAddress(&pxA, g_xA);
    cudaGetSymbolAddress(&pyA, g_yA);
    cudaGetSymbolAddress(&poA, g_oA);
    cudaGetSymbolAddress(&pWq, g_WqB);
    cudaGetSymbolAddress(&pWk, g_WkB);
    cudaGetSymbolAddress(&pWv, g_WvB);
    cudaGetSymbolAddress(&pWo, g_WoB);

    cudaFuncSetAttribute(gemm_f16, cudaFuncAttributeMaxDynamicSharedMemorySize, GT_SMEM);
    cudaFuncSetAttribute(attn_f16, cudaFuncAttributeMaxDynamicSharedMemorySize, AT_SMEM);

    const int M = B_ * T_;                 // 4096
    dim3 ggrid(DM_ / 128, M / 128);        // (8, 32)

    // operand conversions
    convA1024<<<8192, 256>>>(x, (unsigned*)pxA);
    convA1024<<<8192, 256>>>(y, (unsigned*)pyA);
    convB1024<<<2048, 256>>>(Wq, (unsigned*)pWq);
    convB1024<<<2048, 256>>>(Wk, (unsigned*)pWk);
    convB1024<<<2048, 256>>>(Wv, (unsigned*)pWv);
    convB1024<<<2048, 256>>>(Wo, (unsigned*)pWo);

    gemm_f16<<<ggrid, 256, GT_SMEM>>>((const uint4*)pxA, (const uint4*)pWq, (float*)pq, M, DM_, DM_);
    gemm_f16<<<ggrid, 256, GT_SMEM>>>((const uint4*)pyA, (const uint4*)pWk, (float*)pk, M, DM_, DM_);
    gemm_f16<<<ggrid, 256, GT_SMEM>>>((const uint4*)pyA, (const uint4*)pWv, (float*)pv, M, DM_, DM_);

    rope_kernel<<<4096, 256>>>((float*)pq, cosb, sinb);
    rope_kernel<<<4096, 256>>>((float*)pk, cosb, sinb);

    attn_f16<<<dim3(T_ / 128, H_, B_), 256, AT_SMEM>>>(
        (const float*)pq, (const float*)pk, (const float*)pv, mask, (float*)po);

    convA1024<<<8192, 256>>>((const float*)po, (unsigned*)poA);
    gemm_f16<<<ggrid, 256, GT_SMEM>>>((const uint4*)poA, (const uint4*)pWo, out, M, DM_, DM_);
}

// round 5
// speedup vs baseline: 6.4238x; 1.5791x over previous
#include <cuda_runtime.h>
#include <cuda_fp16.h>
#include <cstdint>

#define B_  2
#define T_  2048
#define S_  2048
#define H_  16
#define HD_ 64
#define DM_ 1024

// Scratch (allocation-free rule: __device__ globals)
__device__ float    g_v[B_*S_*H_*HD_];
__device__ unsigned g_xA[B_*T_*DM_/2];
__device__ unsigned g_yA[B_*S_*DM_/2];
__device__ unsigned g_oA[B_*T_*DM_/2];
__device__ unsigned g_WqB[DM_*DM_/2];
__device__ unsigned g_WkB[DM_*DM_/2];
__device__ unsigned g_WvB[DM_*DM_/2];
__device__ unsigned g_WoB[DM_*DM_/2];
__device__ unsigned g_Qf[2*1024*1024];
__device__ unsigned g_Kf[2*1024*1024];
__device__ unsigned g_Vf[2*1024*1024];
__device__ int      g_flags[1024];

// ---------------------------------------------------------------------------
// helpers
// ---------------------------------------------------------------------------
__device__ __forceinline__ unsigned packh2(float a, float b) {
    __half2 h = __floats2half2_rn(a, b);
    return *(unsigned*)&h;
}

__device__ __forceinline__ void mma16(float c[4], const unsigned a[4], const unsigned b[2]) {
    asm volatile(
        "mma.sync.aligned.m16n8k16.row.col.f32.f16.f16.f32 "
        "{%0,%1,%2,%3}, {%4,%5,%6,%7}, {%8,%9}, {%0,%1,%2,%3};"
        : "+f"(c[0]), "+f"(c[1]), "+f"(c[2]), "+f"(c[3])
        : "r"(a[0]), "r"(a[1]), "r"(a[2]), "r"(a[3]), "r"(b[0]), "r"(b[1]));
}

__device__ __forceinline__ uint32_t smem_u32(const void* p) {
    uint32_t a;
    asm("{ .reg .u64 t; cvta.to.shared.u64 t, %1; cvt.u32.u64 %0, t; }" : "=r"(a) : "l"(p));
    return a;
}

#define CP_ASYNC16(dst, src) \
    asm volatile("cp.async.cg.shared.global [%0], [%1], 16;" :: "r"(dst), "l"(src) : "memory")
#define CP_COMMIT() asm volatile("cp.async.commit_group;" ::: "memory")
#define CP_WAIT1()  asm volatile("cp.async.wait_group 1;" ::: "memory")
#define CP_WAIT0()  asm volatile("cp.async.wait_group 0;" ::: "memory")

// ---------------------------------------------------------------------------
// fp32 row-major [M x 1024] -> fp16 A-fragment order
// ---------------------------------------------------------------------------
__global__ __launch_bounds__(256)
void convA1024(const float* __restrict__ src, unsigned* __restrict__ dst) {
    size_t idx = (size_t)blockIdx.x * 256 + threadIdx.x;
    int row = (int)(idx >> 9);
    int c   = (int)(idx & 511) << 1;
    float2 v = *(const float2*)&src[(size_t)row * 1024 + c];
    int mt = row >> 4, rr = row & 15, g = rr & 7, hr = rr >> 3;
    int kt = c >> 4, cc = c & 15, tig = (cc >> 1) & 3, hc = cc >> 3;
    dst[((size_t)(mt * 64 + kt) << 7) + ((g * 4 + tig) << 2) + hr + 2 * hc] =
        packh2(v.x, v.y);
}

// W fp32 [1024 x 1024] -> fp16 B-fragment order
__global__ __launch_bounds__(256)
void convB1024(const float* __restrict__ W, unsigned* __restrict__ dst) {
    size_t idx = (size_t)blockIdx.x * 256 + threadIdx.x;
    int n = (int)(idx & 1023);
    int k = (int)(idx >> 10) << 1;
    float lo = W[(size_t)k * 1024 + n];
    float hi = W[(size_t)(k + 1) * 1024 + n];
    int kt = k >> 4, kk = k & 15, hb = kk >> 3, tig = (kk & 7) >> 1;
    int nt = n >> 3, g = n & 7;
    dst[((size_t)(kt * 128 + nt) << 6) + ((g * 4 + tig) << 1) + hb] = packh2(lo, hi);
}

// V fp32 (b,s,h,d) -> B-frags per (b,h): [kt=s>>4][nt=d>>3][64 u32]
__global__ __launch_bounds__(256)
void convVf(const float* __restrict__ v, unsigned* __restrict__ Vf) {
    int idx = blockIdx.x * 256 + threadIdx.x;
    int d  = idx & 63;
    int h  = (idx >> 6) & 15;
    int sp = (idx >> 10) & 1023;
    int b  = idx >> 20;
    int s0 = sp * 2;
    const float* base = v + ((size_t)(b * 2048 + s0) * 16 + h) * 64 + d;
    float f0 = base[0];
    float f1 = base[1024];
    int bh = b * 16 + h;
    int kt = s0 >> 4, ss = s0 & 15, tg = (ss & 7) >> 1, hb = ss >> 3;
    int nt = d >> 3, dg = d & 7;
    Vf[(size_t)bh * 65536 + (kt << 9) + (nt << 6) + ((dg * 4 + tg) << 1) + hb] =
        packh2(f0, f1);
}

// mask -> per-(b, tblock128, sblock64) nonzero flags
__global__ __launch_bounds__(256)
void maskflags(const float* __restrict__ mask, int* __restrict__ flags) {
    int sb = blockIdx.x, tb = blockIdx.y, b = blockIdx.z;
    const float* mb = mask + ((size_t)(b * 2048 + tb * 128)) * 2048 + sb * 64;
    int nz = 0;
    int row0 = threadIdx.x >> 4;
    int c4   = (threadIdx.x & 15) << 2;
    #pragma unroll
    for (int r = 0; r < 8; r++) {
        float4 v = *(const float4*)&mb[(size_t)(row0 + r * 16) * 2048 + c4];
        nz |= (v.x != 0.f) | (v.y != 0.f) | (v.z != 0.f) | (v.w != 0.f);
    }
    nz = __syncthreads_or(nz);
    if (threadIdx.x == 0) flags[(b * 16 + tb) * 32 + sb] = nz;
}

// ---------------------------------------------------------------------------
// fp16 tensor-core GEMM, 128x128x32, 3-stage cp.async.
// MODE 0: fp32 C. MODE 1: fused rope+scale -> Qf frags. MODE 2: rope -> Kf.
// ---------------------------------------------------------------------------
#define GT_SMEM 49152

template<int MODE>
__global__ __launch_bounds__(256)
void gemm_f16_t(const uint4* __restrict__ Af, const uint4* __restrict__ Bf,
                float* __restrict__ C, unsigned* __restrict__ Fout,
                const float* __restrict__ cosb, const float* __restrict__ sinb,
                int M, int N, int K) {
    extern __shared__ unsigned sm16[];
    const uint32_t sb = smem_u32(sm16);
    const int tid  = threadIdx.x;
    const int lane = tid & 31;
    const int wid  = tid >> 5;
    const int warp_m = wid >> 2;
    const int warp_n = wid & 3;
    const int g   = lane >> 2;
    const int tig = lane & 3;
    const int bm = blockIdx.y * 128;
    const int bn = blockIdx.x * 128;
    const int ktiles = K >> 4;
    const int ntiles = N >> 3;
    const int nkb = K >> 5;

    float acc[4][4][4];
    #pragma unroll
    for (int i = 0; i < 4; i++)
        #pragma unroll
        for (int j = 0; j < 4; j++)
            #pragma unroll
            for (int r = 0; r < 4; r++) acc[i][j][r] = 0.f;

    auto issue = [&](int kb, int buf) {
        #pragma unroll
        for (int u = 0; u < 2; u++) {
            int i = tid + u * 256;
            int ti = i >> 5, mt = ti >> 1, kt = ti & 1;
            size_t gt = (size_t)((bm >> 4) + mt) * ktiles + kb * 2 + kt;
            CP_ASYNC16(sb + (buf * 4096 + ti * 128 + (i & 31) * 4) * 4,
                       Af + gt * 32 + (i & 31));
            int tj = i >> 4, bkt = tj >> 4, nt = tj & 15;
            size_t gtb = (size_t)(kb * 2 + bkt) * ntiles + (bn >> 3) + nt;
            CP_ASYNC16(sb + (buf * 4096 + 2048 + tj * 64 + (i & 15) * 4) * 4,
                       Bf + gtb * 16 + (i & 15));
        }
        CP_COMMIT();
    };

    issue(0, 0);
    issue(1, 1);

    for (int kb = 0; kb < nkb; kb++) {
        if (kb + 2 < nkb) { CP_WAIT1(); } else { CP_WAIT0(); }
        __syncthreads();
        if (kb + 2 < nkb) issue(kb + 2, (kb + 2) % 3);

        const int buf = kb % 3;
        const unsigned* aw = sm16 + buf * 4096;
        const unsigned* bw = aw + 2048;
        #pragma unroll
        for (int kt = 0; kt < 2; kt++) {
            unsigned a[4][4], b[4][2];
            #pragma unroll
            for (int im = 0; im < 4; im++)
                *(uint4*)a[im] = *(const uint4*)&aw[(((warp_m * 4 + im) * 2 + kt) << 7) + lane * 4];
            #pragma unroll
            for (int in_ = 0; in_ < 4; in_++)
                *(uint2*)b[in_] = *(const uint2*)&bw[((kt * 16 + warp_n * 4 + in_) << 6) + lane * 2];
            #pragma unroll
            for (int im = 0; im < 4; im++)
                #pragma unroll
                for (int in_ = 0; in_ < 4; in_++)
                    mma16(acc[im][in_], a[im], b[in_]);
        }
        __syncthreads();
    }

    if (MODE == 0) {
        #pragma unroll
        for (int im = 0; im < 4; im++) {
            int r0 = bm + warp_m * 64 + im * 16 + g;
            #pragma unroll
            for (int in_ = 0; in_ < 4; in_++) {
                int cc = bn + warp_n * 32 + in_ * 8 + tig * 2;
                *(float2*)&C[(size_t)r0 * N + cc]       = make_float2(acc[im][in_][0], acc[im][in_][1]);
                *(float2*)&C[(size_t)(r0 + 8) * N + cc] = make_float2(acc[im][in_][2], acc[im][in_][3]);
            }
        }
    } else {
        const float QS = (MODE == 1) ? 0.125f : 1.0f;
        #pragma unroll
        for (int im = 0; im < 4; im++) {
            int row = bm + warp_m * 64 + im * 16 + g;
            int b = row >> 11, t = row & 2047;
            float v[4][4];
            #pragma unroll
            for (int j = 0; j < 4; j++)
                #pragma unroll
                for (int r = 0; r < 4; r++) v[j][r] = acc[im][j][r];
            if ((warp_n & 1) == 0) {   // d in [0,32): partial rope
                #pragma unroll
                for (int in0 = 0; in0 < 2; in0++) {
                    #pragma unroll
                    for (int e = 0; e < 2; e++) {
                        int d = in0 * 8 + tig * 2 + e;
                        float cl = cosb[t * 16 + d],       sl = sinb[t * 16 + d];
                        float ch = cosb[(t + 8) * 16 + d], sh = sinb[(t + 8) * 16 + d];
                        float x1 = v[in0][e],     x2 = v[in0 + 2][e];
                        v[in0][e]       = x1 * cl - x2 * sl;
                        v[in0 + 2][e]   = x2 * cl + x1 * sl;
                        float y1 = v[in0][2 + e], y2 = v[in0 + 2][2 + e];
                        v[in0][2 + e]     = y1 * ch - y2 * sh;
                        v[in0 + 2][2 + e] = y2 * ch + y1 * sh;
                    }
                }
            }
            #pragma unroll
            for (int p = 0; p < 2; p++) {
                int in0 = 2 * p, in1 = 2 * p + 1;
                int cc = bn + warp_n * 32 + in0 * 8;
                int h = (cc >> 6) & 15, d = cc & 63, kt = d >> 4;
                int bh = b * 16 + h;
                if (MODE == 1) {
                    int mt = t >> 4;
                    uint4 w;
                    w.x = packh2(v[in0][0] * QS, v[in0][1] * QS);
                    w.y = packh2(v[in0][2] * QS, v[in0][3] * QS);
                    w.z = packh2(v[in1][0] * QS, v[in1][1] * QS);
                    w.w = packh2(v[in1][2] * QS, v[in1][3] * QS);
                    *(uint4*)&Fout[(size_t)bh * 65536 + ((size_t)(mt * 4 + kt) << 7) + lane * 4] = w;
                } else {
                    int nt = t >> 3;   // key position
                    size_t base = (size_t)bh * 65536 + ((size_t)nt << 8) + (kt << 6) + (g * 4 + tig) * 2;
                    *(uint2*)&Fout[base] =
                        make_uint2(packh2(v[in0][0], v[in0][1]), packh2(v[in1][0], v[in1][1]));
                    *(uint2*)&Fout[base + 256] =
                        make_uint2(packh2(v[in0][2], v[in0][3]), packh2(v[in1][2], v[in1][3]));
                }
            }
        }
    }
}

// ---------------------------------------------------------------------------
// Fused flash attention on pre-fragmented fp16 operands.
// ---------------------------------------------------------------------------
#define AT_SMEM (16384 * 4)

__global__ __launch_bounds__(256, 2)
void attn_f16(const uint4* __restrict__ Qf, const uint4* __restrict__ Kf,
              const uint4* __restrict__ Vf, const float* __restrict__ mask,
              const int* __restrict__ flags, unsigned* __restrict__ Of) {
    extern __shared__ unsigned sma[];
    const uint32_t sb = smem_u32(sma);
    const int tid  = threadIdx.x;
    const int lane = tid & 31;
    const int wid  = tid >> 5;
    const int g    = lane >> 2;
    const int tig  = lane & 3;
    const int tb   = blockIdx.x;
    const int h    = blockIdx.y;
    const int b    = blockIdx.z;
    const int t0   = tb * 128;
    const int bh   = b * 16 + h;

    {
        size_t qb = (size_t)bh * 16384 + (size_t)(t0 >> 4) * 128;
        #pragma unroll
        for (int u = 0; u < 4; u++) {
            int c = tid + u * 256;
            CP_ASYNC16(sb + c * 16, Qf + qb + c);
        }
    }
    auto issueKV = [&](int s0, int buf) {
        size_t kb = (size_t)bh * 16384 + (size_t)(s0 >> 3) * 64;
        size_t vb = (size_t)bh * 16384 + (size_t)(s0 >> 4) * 128;
        #pragma unroll
        for (int u = 0; u < 2; u++) {
            int c = tid + u * 256;
            CP_ASYNC16(sb + (4096 + buf * 4096 + c * 4) * 4, Kf + kb + c);
            CP_ASYNC16(sb + (6144 + buf * 4096 + c * 4) * 4, Vf + vb + c);
        }
    };
    issueKV(0, 0);  CP_COMMIT();
    issueKV(64, 1); CP_COMMIT();

    float m_[2] = {-1e30f, -1e30f};
    float l_[2] = {0.f, 0.f};
    float acc[8][4];
    #pragma unroll
    for (int nt = 0; nt < 8; nt++)
        #pragma unroll
        for (int r = 0; r < 4; r++) acc[nt][r] = 0.f;

    const int nT = S_ / 64;
    for (int i = 0; i < nT; i++) {
        if (i + 1 < nT) { CP_WAIT1(); } else { CP_WAIT0(); }
        __syncthreads();
        const int buf = i & 1;
        const unsigned* kw = sma + 4096 + buf * 4096;
        const unsigned* vw = sma + 6144 + buf * 4096;

        float sc[8][4];
        int mz = __ldg(&flags[(b * 16 + tb) * 32 + i]);
        if (mz) {
            const float* mr0 = &mask[((size_t)b * T_ + t0 + wid * 16 + g) * S_ + i * 64];
            const float* mr1 = mr0 + 8 * S_;
            #pragma unroll
            for (int nt = 0; nt < 8; nt++) {
                float2 m0 = *(const float2*)&mr0[nt * 8 + 2 * tig];
                float2 m1 = *(const float2*)&mr1[nt * 8 + 2 * tig];
                sc[nt][0] = m0.x; sc[nt][1] = m0.y;
                sc[nt][2] = m1.x; sc[nt][3] = m1.y;
            }
        } else {
            #pragma unroll
            for (int nt = 0; nt < 8; nt++)
                #pragma unroll
                for (int r = 0; r < 4; r++) sc[nt][r] = 0.f;
        }

        #pragma unroll
        for (int kt = 0; kt < 4; kt++) {
            unsigned a[4];
            *(uint4*)a = *(const uint4*)&sma[((wid * 4 + kt) << 7) + lane * 4];
            #pragma unroll
            for (int nt = 0; nt < 8; nt++) {
                unsigned bb[2];
                *(uint2*)bb = *(const uint2*)&kw[((nt * 4 + kt) << 6) + lane * 2];
                mma16(sc[nt], a, bb);
            }
        }

        #pragma unroll
        for (int e = 0; e < 2; e++) {
            float tmax = -1e30f;
            #pragma unroll
            for (int nt = 0; nt < 8; nt++)
                tmax = fmaxf(tmax, fmaxf(sc[nt][2 * e], sc[nt][2 * e + 1]));
            tmax = fmaxf(tmax, __shfl_xor_sync(0xffffffffu, tmax, 1));
            tmax = fmaxf(tmax, __shfl_xor_sync(0xffffffffu, tmax, 2));
            float mnew  = fmaxf(m_[e], tmax);
            float alpha = __expf(m_[e] - mnew);
            m_[e] = mnew;
            float ps = 0.f;
            #pragma unroll
            for (int nt = 0; nt < 8; nt++) {
                float p0 = __expf(sc[nt][2 * e]     - mnew);
                float p1 = __expf(sc[nt][2 * e + 1] - mnew);
                sc[nt][2 * e] = p0; sc[nt][2 * e + 1] = p1;
                ps += p0 + p1;
            }
            ps += __shfl_xor_sync(0xffffffffu, ps, 1);
            ps += __shfl_xor_sync(0xffffffffu, ps, 2);
            l_[e] = l_[e] * alpha + ps;
            #pragma unroll
            for (int nt = 0; nt < 8; nt++) {
                acc[nt][2 * e]     *= alpha;
                acc[nt][2 * e + 1] *= alpha;
            }
        }

        unsigned* pw = sma + 12288 + wid * 512;
        #pragma unroll
        for (int nt = 0; nt < 8; nt++) {
            #pragma unroll
            for (int hr = 0; hr < 2; hr++) {
                pw[((nt >> 1) << 7) + lane * 4 + hr + 2 * (nt & 1)] =
                    packh2(sc[nt][2 * hr], sc[nt][2 * hr + 1]);
            }
        }
        __syncwarp();

        #pragma unroll
        for (int kt = 0; kt < 4; kt++) {
            unsigned a[4];
            *(uint4*)a = *(const uint4*)&pw[(kt << 7) + lane * 4];
            #pragma unroll
            for (int nt = 0; nt < 8; nt++) {
                unsigned bb[2];
                *(uint2*)bb = *(const uint2*)&vw[((kt * 8 + nt) << 6) + lane * 2];
                mma16(acc[nt], a, bb);
            }
        }
        __syncthreads();
        if (i + 2 < nT) { issueKV((i + 2) * 64, buf); CP_COMMIT(); }
    }

    float inv0 = 1.f / l_[0];
    float inv1 = 1.f / l_[1];
    int mt_g = (b * 2048 + t0 + wid * 16) >> 4;
    #pragma unroll
    for (int kt = 0; kt < 4; kt++) {
        int nt0 = 2 * kt, nt1 = nt0 + 1;
        uint4 w;
        w.x = packh2(acc[nt0][0] * inv0, acc[nt0][1] * inv0);
        w.y = packh2(acc[nt0][2] * inv1, acc[nt0][3] * inv1);
        w.z = packh2(acc[nt1][0] * inv0, acc[nt1][1] * inv0);
        w.w = packh2(acc[nt1][2] * inv1, acc[nt1][3] * inv1);
        int kt_g = h * 4 + kt;
        *(uint4*)&Of[((size_t)(mt_g * 64 + kt_g) << 7) + lane * 4] = w;
    }
}

// ---------------------------------------------------------------------------
extern "C" void kernel_launch(void* const* d_in, const int* in_sizes, int n_in,
                              void* d_out, int out_size) {
    const float* x    = (const float*)d_in[0];
    const float* y    = (const float*)d_in[1];
    const float* cosb = (const float*)d_in[2];
    const float* sinb = (const float*)d_in[3];
    const float* mask = (const float*)d_in[4];
    const float* Wq   = (const float*)d_in[5];
    const float* Wk   = (const float*)d_in[6];
    const float* Wv   = (const float*)d_in[7];
    const float* Wo   = (const float*)d_in[8];
    float* out = (float*)d_out;

    void *pv, *pxA, *pyA, *poA, *pWq, *pWk, *pWv, *pWo, *pQf, *pKf, *pVf, *pfl;
    cudaGetSymbolAddress(&pv, g_v);
    cudaGetSymbolAddress(&pxA, g_xA);
    cudaGetSymbolAddress(&pyA, g_yA);
    cudaGetSymbolAddress(&poA, g_oA);
    cudaGetSymbolAddress(&pWq, g_WqB);
    cudaGetSymbolAddress(&pWk, g_WkB);
    cudaGetSymbolAddress(&pWv, g_WvB);
    cudaGetSymbolAddress(&pWo, g_WoB);
    cudaGetSymbolAddress(&pQf, g_Qf);
    cudaGetSymbolAddress(&pKf, g_Kf);
    cudaGetSymbolAddress(&pVf, g_Vf);
    cudaGetSymbolAddress(&pfl, g_flags);

    cudaFuncSetAttribute(gemm_f16_t<0>, cudaFuncAttributeMaxDynamicSharedMemorySize, GT_SMEM);
    cudaFuncSetAttribute(gemm_f16_t<1>, cudaFuncAttributeMaxDynamicSharedMemorySize, GT_SMEM);
    cudaFuncSetAttribute(gemm_f16_t<2>, cudaFuncAttributeMaxDynamicSharedMemorySize, GT_SMEM);
    cudaFuncSetAttribute(attn_f16, cudaFuncAttributeMaxDynamicSharedMemorySize, AT_SMEM);

    const int M = B_ * T_;                 // 4096
    dim3 ggrid(DM_ / 128, M / 128);        // (8, 32)

    convA1024<<<8192, 256>>>(x, (unsigned*)pxA);
    convA1024<<<8192, 256>>>(y, (unsigned*)pyA);
    convB1024<<<2048, 256>>>(Wq, (unsigned*)pWq);
    convB1024<<<2048, 256>>>(Wk, (unsigned*)pWk);
    convB1024<<<2048, 256>>>(Wv, (unsigned*)pWv);
    convB1024<<<2048, 256>>>(Wo, (unsigned*)pWo);
    maskflags<<<dim3(32, 16, 2), 256>>>(mask, (int*)pfl);

    gemm_f16_t<1><<<ggrid, 256, GT_SMEM>>>((const uint4*)pxA, (const uint4*)pWq,
        nullptr, (unsigned*)pQf, cosb, sinb, M, DM_, DM_);
    gemm_f16_t<2><<<ggrid, 256, GT_SMEM>>>((const uint4*)pyA, (const uint4*)pWk,
        nullptr, (unsigned*)pKf, cosb, sinb, M, DM_, DM_);
    gemm_f16_t<0><<<ggrid, 256, GT_SMEM>>>((const uint4*)pyA, (const uint4*)pWv,
        (float*)pv, nullptr, nullptr, nullptr, M, DM_, DM_);
    convVf<<<8192, 256>>>((const float*)pv, (unsigned*)pVf);

    attn_f16<<<dim3(T_ / 128, H_, B_), 256, AT_SMEM>>>(
        (const uint4*)pQf, (const uint4*)pKf, (const uint4*)pVf,
        mask, (const int*)pfl, (unsigned*)poA);

    gemm_f16_t<0><<<ggrid, 256, GT_SMEM>>>((const uint4*)poA, (const uint4*)pWo,
        out, nullptr, nullptr, nullptr, M, DM_, DM_);
}

// round 6
// speedup vs baseline: 7.2991x; 1.1363x over previous
#include <cuda_runtime.h>
#include <cuda_fp16.h>
#include <cstdint>

#define B_  2
#define T_  2048
#define S_  2048
#define H_  16
#define HD_ 64
#define DM_ 1024

// Scratch (allocation-free rule: __device__ globals)
__device__ unsigned g_xA[B_*T_*DM_/2];
__device__ unsigned g_yA[B_*S_*DM_/2];
__device__ unsigned g_oA[B_*T_*DM_/2];
__device__ unsigned g_WqB[DM_*DM_/2];
__device__ unsigned g_WkB[DM_*DM_/2];
__device__ unsigned g_WvB[DM_*DM_/2];
__device__ unsigned g_WoB[DM_*DM_/2];
__device__ unsigned g_Qf[2*1024*1024];
__device__ unsigned g_Kf[2*1024*1024];
__device__ unsigned g_Vf[2*1024*1024];
__device__ int      g_flags[1024];

// ---------------------------------------------------------------------------
// helpers
// ---------------------------------------------------------------------------
__device__ __forceinline__ unsigned packh2(float a, float b) {
    __half2 h = __floats2half2_rn(a, b);
    return *(unsigned*)&h;
}

__device__ __forceinline__ void mma16(float c[4], const unsigned a[4], const unsigned b[2]) {
    asm volatile(
        "mma.sync.aligned.m16n8k16.row.col.f32.f16.f16.f32 "
        "{%0,%1,%2,%3}, {%4,%5,%6,%7}, {%8,%9}, {%0,%1,%2,%3};"
        : "+f"(c[0]), "+f"(c[1]), "+f"(c[2]), "+f"(c[3])
        : "r"(a[0]), "r"(a[1]), "r"(a[2]), "r"(a[3]), "r"(b[0]), "r"(b[1]));
}

__device__ __forceinline__ uint32_t smem_u32(const void* p) {
    uint32_t a;
    asm("{ .reg .u64 t; cvta.to.shared.u64 t, %1; cvt.u32.u64 %0, t; }" : "=r"(a) : "l"(p));
    return a;
}

#define CP_ASYNC16(dst, src) \
    asm volatile("cp.async.cg.shared.global [%0], [%1], 16;" :: "r"(dst), "l"(src) : "memory")
#define CP_COMMIT() asm volatile("cp.async.commit_group;" ::: "memory")
#define CP_WAIT1()  asm volatile("cp.async.wait_group 1;" ::: "memory")
#define CP_WAIT0()  asm volatile("cp.async.wait_group 0;" ::: "memory")

// ---------------------------------------------------------------------------
// fp32 row-major [M x 1024] -> fp16 A-fragment order
// ---------------------------------------------------------------------------
__global__ __launch_bounds__(256)
void convA1024(const float* __restrict__ src, unsigned* __restrict__ dst) {
    size_t idx = (size_t)blockIdx.x * 256 + threadIdx.x;
    int row = (int)(idx >> 9);
    int c   = (int)(idx & 511) << 1;
    float2 v = *(const float2*)&src[(size_t)row * 1024 + c];
    int mt = row >> 4, rr = row & 15, g = rr & 7, hr = rr >> 3;
    int kt = c >> 4, cc = c & 15, tig = (cc >> 1) & 3, hc = cc >> 3;
    dst[((size_t)(mt * 64 + kt) << 7) + ((g * 4 + tig) << 2) + hr + 2 * hc] =
        packh2(v.x, v.y);
}

// W fp32 [1024 x 1024] -> fp16 B-fragment order
__global__ __launch_bounds__(256)
void convB1024(const float* __restrict__ W, unsigned* __restrict__ dst) {
    size_t idx = (size_t)blockIdx.x * 256 + threadIdx.x;
    int n = (int)(idx & 1023);
    int k = (int)(idx >> 10) << 1;
    float lo = W[(size_t)k * 1024 + n];
    float hi = W[(size_t)(k + 1) * 1024 + n];
    int kt = k >> 4, kk = k & 15, hb = kk >> 3, tig = (kk & 7) >> 1;
    int nt = n >> 3, g = n & 7;
    dst[((size_t)(kt * 128 + nt) << 6) + ((g * 4 + tig) << 1) + hb] = packh2(lo, hi);
}

// mask -> per-(b, tblock128, sblock64) nonzero flags
__global__ __launch_bounds__(256)
void maskflags(const float* __restrict__ mask, int* __restrict__ flags) {
    int sb = blockIdx.x, tb = blockIdx.y, b = blockIdx.z;
    const float* mb = mask + ((size_t)(b * 2048 + tb * 128)) * 2048 + sb * 64;
    int nz = 0;
    int row0 = threadIdx.x >> 4;
    int c4   = (threadIdx.x & 15) << 2;
    #pragma unroll
    for (int r = 0; r < 8; r++) {
        float4 v = *(const float4*)&mb[(size_t)(row0 + r * 16) * 2048 + c4];
        nz |= (v.x != 0.f) | (v.y != 0.f) | (v.z != 0.f) | (v.w != 0.f);
    }
    nz = __syncthreads_or(nz);
    if (threadIdx.x == 0) flags[(b * 16 + tb) * 32 + sb] = nz;
}

// ---------------------------------------------------------------------------
// fp16 tensor-core GEMM, 128x128x32, 3-stage cp.async.
// MODE 0: fp32 C.  MODE 1: rope+scale -> Qf frags.  MODE 2: rope -> Kf frags.
// MODE 3: V B-frags -> Vf (pairs adjacent s rows via shfl).
// ---------------------------------------------------------------------------
#define GT_SMEM 49152

template<int MODE>
__global__ __launch_bounds__(256, 2)
void gemm_f16_t(const uint4* __restrict__ Af, const uint4* __restrict__ Bf,
                float* __restrict__ C, unsigned* __restrict__ Fout,
                const float* __restrict__ cosb, const float* __restrict__ sinb,
                int M, int N, int K) {
    extern __shared__ unsigned sm16[];
    const uint32_t sb = smem_u32(sm16);
    const int tid  = threadIdx.x;
    const int lane = tid & 31;
    const int wid  = tid >> 5;
    const int warp_m = wid >> 2;
    const int warp_n = wid & 3;
    const int g   = lane >> 2;
    const int tig = lane & 3;
    const int bm = blockIdx.y * 128;
    const int bn = blockIdx.x * 128;
    const int ktiles = K >> 4;
    const int ntiles = N >> 3;
    const int nkb = K >> 5;

    float acc[4][4][4];
    #pragma unroll
    for (int i = 0; i < 4; i++)
        #pragma unroll
        for (int j = 0; j < 4; j++)
            #pragma unroll
            for (int r = 0; r < 4; r++) acc[i][j][r] = 0.f;

    auto issue = [&](int kb, int buf) {
        #pragma unroll
        for (int u = 0; u < 2; u++) {
            int i = tid + u * 256;
            int ti = i >> 5, mt = ti >> 1, kt = ti & 1;
            size_t gt = (size_t)((bm >> 4) + mt) * ktiles + kb * 2 + kt;
            CP_ASYNC16(sb + (buf * 4096 + ti * 128 + (i & 31) * 4) * 4,
                       Af + gt * 32 + (i & 31));
            int tj = i >> 4, bkt = tj >> 4, nt = tj & 15;
            size_t gtb = (size_t)(kb * 2 + bkt) * ntiles + (bn >> 3) + nt;
            CP_ASYNC16(sb + (buf * 4096 + 2048 + tj * 64 + (i & 15) * 4) * 4,
                       Bf + gtb * 16 + (i & 15));
        }
        CP_COMMIT();
    };

    issue(0, 0);
    issue(1, 1);

    for (int kb = 0; kb < nkb; kb++) {
        if (kb + 2 < nkb) { CP_WAIT1(); } else { CP_WAIT0(); }
        __syncthreads();
        if (kb + 2 < nkb) issue(kb + 2, (kb + 2) % 3);

        const int buf = kb % 3;
        const unsigned* aw = sm16 + buf * 4096;
        const unsigned* bw = aw + 2048;
        #pragma unroll
        for (int kt = 0; kt < 2; kt++) {
            unsigned a[4][4], b[4][2];
            #pragma unroll
            for (int im = 0; im < 4; im++)
                *(uint4*)a[im] = *(const uint4*)&aw[(((warp_m * 4 + im) * 2 + kt) << 7) + lane * 4];
            #pragma unroll
            for (int in_ = 0; in_ < 4; in_++)
                *(uint2*)b[in_] = *(const uint2*)&bw[((kt * 16 + warp_n * 4 + in_) << 6) + lane * 2];
            #pragma unroll
            for (int im = 0; im < 4; im++)
                #pragma unroll
                for (int in_ = 0; in_ < 4; in_++)
                    mma16(acc[im][in_], a[im], b[in_]);
        }
        __syncthreads();
    }

    if (MODE == 0) {
        #pragma unroll
        for (int im = 0; im < 4; im++) {
            int r0 = bm + warp_m * 64 + im * 16 + g;
            #pragma unroll
            for (int in_ = 0; in_ < 4; in_++) {
                int cc = bn + warp_n * 32 + in_ * 8 + tig * 2;
                *(float2*)&C[(size_t)r0 * N + cc]       = make_float2(acc[im][in_][0], acc[im][in_][1]);
                *(float2*)&C[(size_t)(r0 + 8) * N + cc] = make_float2(acc[im][in_][2], acc[im][in_][3]);
            }
        }
    } else if (MODE == 3) {
        // V: output row = s, col = h*64+d.  Pair (s even, s odd) via shfl_xor 4.
        #pragma unroll
        for (int im = 0; im < 4; im++) {
            int row = bm + warp_m * 64 + im * 16;   // 16-aligned
            int b = row >> 11;
            int s = row & 2047;
            int kt = s >> 4;
            #pragma unroll
            for (int in_ = 0; in_ < 4; in_++) {
                #pragma unroll
                for (int e = 0; e < 2; e++) {
                    float v0 = acc[im][in_][e];       // row g
                    float v1 = acc[im][in_][2 + e];   // row g+8
                    float p0 = __shfl_xor_sync(0xffffffffu, v0, 4);
                    float p1 = __shfl_xor_sync(0xffffffffu, v1, 4);
                    if ((g & 1) == 0) {
                        int cc = bn + warp_n * 32 + in_ * 8 + tig * 2 + e;
                        int h = (cc >> 6) & 15, d = cc & 63;
                        int nt = d >> 3, dg = d & 7;
                        int bh = b * 16 + h;
                        size_t base = (size_t)bh * 65536 + ((size_t)kt << 9) +
                                      (nt << 6) + ((dg * 4 + (g >> 1)) << 1);
                        Fout[base]     = packh2(v0, p0);
                        Fout[base + 1] = packh2(v1, p1);
                    }
                }
            }
        }
    } else {
        const float QS = (MODE == 1) ? 0.125f : 1.0f;
        #pragma unroll
        for (int im = 0; im < 4; im++) {
            int row = bm + warp_m * 64 + im * 16 + g;
            int b = row >> 11, t = row & 2047;
            float v[4][4];
            #pragma unroll
            for (int j = 0; j < 4; j++)
                #pragma unroll
                for (int r = 0; r < 4; r++) v[j][r] = acc[im][j][r];
            if ((warp_n & 1) == 0) {   // d in [0,32): partial rope
                #pragma unroll
                for (int in0 = 0; in0 < 2; in0++) {
                    #pragma unroll
                    for (int e = 0; e < 2; e++) {
                        int d = in0 * 8 + tig * 2 + e;
                        float cl = cosb[t * 16 + d],       sl = sinb[t * 16 + d];
                        float ch = cosb[(t + 8) * 16 + d], sh = sinb[(t + 8) * 16 + d];
                        float x1 = v[in0][e],     x2 = v[in0 + 2][e];
                        v[in0][e]       = x1 * cl - x2 * sl;
                        v[in0 + 2][e]   = x2 * cl + x1 * sl;
                        float y1 = v[in0][2 + e], y2 = v[in0 + 2][2 + e];
                        v[in0][2 + e]     = y1 * ch - y2 * sh;
                        v[in0 + 2][2 + e] = y2 * ch + y1 * sh;
                    }
                }
            }
            #pragma unroll
            for (int p = 0; p < 2; p++) {
                int in0 = 2 * p, in1 = 2 * p + 1;
                int cc = bn + warp_n * 32 + in0 * 8;
                int h = (cc >> 6) & 15, d = cc & 63, kt = d >> 4;
                int bh = b * 16 + h;
                if (MODE == 1) {
                    int mt = t >> 4;
                    uint4 w;
                    w.x = packh2(v[in0][0] * QS, v[in0][1] * QS);
                    w.y = packh2(v[in0][2] * QS, v[in0][3] * QS);
                    w.z = packh2(v[in1][0] * QS, v[in1][1] * QS);
                    w.w = packh2(v[in1][2] * QS, v[in1][3] * QS);
                    *(uint4*)&Fout[(size_t)bh * 65536 + ((size_t)(mt * 4 + kt) << 7) + lane * 4] = w;
                } else {
                    int nt = t >> 3;   // key position
                    size_t base = (size_t)bh * 65536 + ((size_t)nt << 8) + (kt << 6) + (g * 4 + tig) * 2;
                    *(uint2*)&Fout[base] =
                        make_uint2(packh2(v[in0][0], v[in0][1]), packh2(v[in1][0], v[in1][1]));
                    *(uint2*)&Fout[base + 256] =
                        make_uint2(packh2(v[in0][2], v[in0][3]), packh2(v[in1][2], v[in1][3]));
                }
            }
        }
    }
}

// ---------------------------------------------------------------------------
// Fused flash attention: Q and P register-resident, KV double-buffered
// cp.async (32KB smem), mask gated by zero-tile flags, output as A-frags.
// smem u32: k0[0,2048) v0[2048,4096) | k1[4096,6144) v1[6144,8192)
// ---------------------------------------------------------------------------
#define AT_SMEM (8192 * 4)

__global__ __launch_bounds__(256, 2)
void attn_f16(const uint4* __restrict__ Qf, const uint4* __restrict__ Kf,
              const uint4* __restrict__ Vf, const float* __restrict__ mask,
              const int* __restrict__ flags, unsigned* __restrict__ Of) {
    extern __shared__ unsigned sma[];
    const uint32_t sb = smem_u32(sma);
    const int tid  = threadIdx.x;
    const int lane = tid & 31;
    const int wid  = tid >> 5;
    const int g    = lane >> 2;
    const int tig  = lane & 3;
    const int tb   = blockIdx.x;
    const int h    = blockIdx.y;
    const int b    = blockIdx.z;
    const int t0   = tb * 128;
    const int bh   = b * 16 + h;

    auto issueKV = [&](int s0, int buf) {
        size_t kb = (size_t)bh * 16384 + (size_t)(s0 >> 3) * 64;
        size_t vb = (size_t)bh * 16384 + (size_t)(s0 >> 4) * 128;
        #pragma unroll
        for (int u = 0; u < 2; u++) {
            int c = tid + u * 256;
            CP_ASYNC16(sb + (buf * 4096 + c * 4) * 4,        Kf + kb + c);
            CP_ASYNC16(sb + (buf * 4096 + 2048 + c * 4) * 4, Vf + vb + c);
        }
    };
    issueKV(0, 0);  CP_COMMIT();
    issueKV(64, 1); CP_COMMIT();

    // Q fragments into registers (warp's own 16 rows, all 64 d)
    unsigned qr[4][4];
    {
        int mt = (t0 >> 4) + wid;
        #pragma unroll
        for (int kt = 0; kt < 4; kt++)
            *(uint4*)qr[kt] = Qf[(size_t)bh * 16384 + (size_t)(mt * 4 + kt) * 32 + lane];
    }

    float m_[2] = {-1e30f, -1e30f};
    float l_[2] = {0.f, 0.f};
    float acc[8][4];
    #pragma unroll
    for (int nt = 0; nt < 8; nt++)
        #pragma unroll
        for (int r = 0; r < 4; r++) acc[nt][r] = 0.f;

    const int nT = S_ / 64;
    for (int i = 0; i < nT; i++) {
        if (i + 1 < nT) { CP_WAIT1(); } else { CP_WAIT0(); }
        __syncthreads();
        const int buf = i & 1;
        const unsigned* kw = sma + buf * 4096;
        const unsigned* vw = kw + 2048;

        float sc[8][4];
        int mz = __ldg(&flags[(b * 16 + tb) * 32 + i]);
        if (mz) {
            const float* mr0 = &mask[((size_t)b * T_ + t0 + wid * 16 + g) * S_ + i * 64];
            const float* mr1 = mr0 + 8 * S_;
            #pragma unroll
            for (int nt = 0; nt < 8; nt++) {
                float2 m0 = *(const float2*)&mr0[nt * 8 + 2 * tig];
                float2 m1 = *(const float2*)&mr1[nt * 8 + 2 * tig];
                sc[nt][0] = m0.x; sc[nt][1] = m0.y;
                sc[nt][2] = m1.x; sc[nt][3] = m1.y;
            }
        } else {
            #pragma unroll
            for (int nt = 0; nt < 8; nt++)
                #pragma unroll
                for (int r = 0; r < 4; r++) sc[nt][r] = 0.f;
        }

        // scores += Q @ K^T  (Q in registers)
        #pragma unroll
        for (int kt = 0; kt < 4; kt++) {
            #pragma unroll
            for (int nt = 0; nt < 8; nt++) {
                unsigned bb[2];
                *(uint2*)bb = *(const uint2*)&kw[((nt * 4 + kt) << 6) + lane * 2];
                mma16(sc[nt], qr[kt], bb);
            }
        }

        // online softmax (warp-local)
        #pragma unroll
        for (int e = 0; e < 2; e++) {
            float tmax = -1e30f;
            #pragma unroll
            for (int nt = 0; nt < 8; nt++)
                tmax = fmaxf(tmax, fmaxf(sc[nt][2 * e], sc[nt][2 * e + 1]));
            tmax = fmaxf(tmax, __shfl_xor_sync(0xffffffffu, tmax, 1));
            tmax = fmaxf(tmax, __shfl_xor_sync(0xffffffffu, tmax, 2));
            float mnew  = fmaxf(m_[e], tmax);
            float alpha = __expf(m_[e] - mnew);
            m_[e] = mnew;
            float ps = 0.f;
            #pragma unroll
            for (int nt = 0; nt < 8; nt++) {
                float p0 = __expf(sc[nt][2 * e]     - mnew);
                float p1 = __expf(sc[nt][2 * e + 1] - mnew);
                sc[nt][2 * e] = p0; sc[nt][2 * e + 1] = p1;
                ps += p0 + p1;
            }
            ps += __shfl_xor_sync(0xffffffffu, ps, 1);
            ps += __shfl_xor_sync(0xffffffffu, ps, 2);
            l_[e] = l_[e] * alpha + ps;
            #pragma unroll
            for (int nt = 0; nt < 8; nt++) {
                acc[nt][2 * e]     *= alpha;
                acc[nt][2 * e + 1] *= alpha;
            }
        }

        // acc += P @ V   (P A-fragments built directly in registers)
        #pragma unroll
        for (int kt = 0; kt < 4; kt++) {
            unsigned a[4];
            a[0] = packh2(sc[2 * kt][0],     sc[2 * kt][1]);
            a[1] = packh2(sc[2 * kt][2],     sc[2 * kt][3]);
            a[2] = packh2(sc[2 * kt + 1][0], sc[2 * kt + 1][1]);
            a[3] = packh2(sc[2 * kt + 1][2], sc[2 * kt + 1][3]);
            #pragma unroll
            for (int nt = 0; nt < 8; nt++) {
                unsigned bb[2];
                *(uint2*)bb = *(const uint2*)&vw[((kt * 8 + nt) << 6) + lane * 2];
                mma16(acc[nt], a, bb);
            }
        }
        __syncthreads();
        if (i + 2 < nT) { issueKV((i + 2) * 64, buf); CP_COMMIT(); }
    }

    float inv0 = 1.f / l_[0];
    float inv1 = 1.f / l_[1];
    int mt_g = (b * 2048 + t0 + wid * 16) >> 4;
    #pragma unroll
    for (int kt = 0; kt < 4; kt++) {
        int nt0 = 2 * kt, nt1 = nt0 + 1;
        uint4 w;
        w.x = packh2(acc[nt0][0] * inv0, acc[nt0][1] * inv0);
        w.y = packh2(acc[nt0][2] * inv1, acc[nt0][3] * inv1);
        w.z = packh2(acc[nt1][0] * inv0, acc[nt1][1] * inv0);
        w.w = packh2(acc[nt1][2] * inv1, acc[nt1][3] * inv1);
        int kt_g = h * 4 + kt;
        *(uint4*)&Of[((size_t)(mt_g * 64 + kt_g) << 7) + lane * 4] = w;
    }
}

// ---------------------------------------------------------------------------
extern "C" void kernel_launch(void* const* d_in, const int* in_sizes, int n_in,
                              void* d_out, int out_size) {
    const float* x    = (const float*)d_in[0];
    const float* y    = (const float*)d_in[1];
    const float* cosb = (const float*)d_in[2];
    const float* sinb = (const float*)d_in[3];
    const float* mask = (const float*)d_in[4];
    const float* Wq   = (const float*)d_in[5];
    const float* Wk   = (const float*)d_in[6];
    const float* Wv   = (const float*)d_in[7];
    const float* Wo   = (const float*)d_in[8];
    float* out = (float*)d_out;

    void *pxA, *pyA, *poA, *pWq, *pWk, *pWv, *pWo, *pQf, *pKf, *pVf, *pfl;
    cudaGetSymbolAddress(&pxA, g_xA);
    cudaGetSymbolAddress(&pyA, g_yA);
    cudaGetSymbolAddress(&poA, g_oA);
    cudaGetSymbolAddress(&pWq, g_WqB);
    cudaGetSymbolAddress(&pWk, g_WkB);
    cudaGetSymbolAddress(&pWv, g_WvB);
    cudaGetSymbolAddress(&pWo, g_WoB);
    cudaGetSymbolAddress(&pQf, g_Qf);
    cudaGetSymbolAddress(&pKf, g_Kf);
    cudaGetSymbolAddress(&pVf, g_Vf);
    cudaGetSymbolAddress(&pfl, g_flags);

    cudaFuncSetAttribute(gemm_f16_t<0>, cudaFuncAttributeMaxDynamicSharedMemorySize, GT_SMEM);
    cudaFuncSetAttribute(gemm_f16_t<1>, cudaFuncAttributeMaxDynamicSharedMemorySize, GT_SMEM);
    cudaFuncSetAttribute(gemm_f16_t<2>, cudaFuncAttributeMaxDynamicSharedMemorySize, GT_SMEM);
    cudaFuncSetAttribute(gemm_f16_t<3>, cudaFuncAttributeMaxDynamicSharedMemorySize, GT_SMEM);
    cudaFuncSetAttribute(attn_f16, cudaFuncAttributeMaxDynamicSharedMemorySize, AT_SMEM);

    const int M = B_ * T_;                 // 4096
    dim3 ggrid(DM_ / 128, M / 128);        // (8, 32)

    convA1024<<<8192, 256>>>(x, (unsigned*)pxA);
    convA1024<<<8192, 256>>>(y, (unsigned*)pyA);
    convB1024<<<2048, 256>>>(Wq, (unsigned*)pWq);
    convB1024<<<2048, 256>>>(Wk, (unsigned*)pWk);
    convB1024<<<2048, 256>>>(Wv, (unsigned*)pWv);
    convB1024<<<2048, 256>>>(Wo, (unsigned*)pWo);
    maskflags<<<dim3(32, 16, 2), 256>>>(mask, (int*)pfl);

    gemm_f16_t<1><<<ggrid, 256, GT_SMEM>>>((const uint4*)pxA, (const uint4*)pWq,
        nullptr, (unsigned*)pQf, cosb, sinb, M, DM_, DM_);
    gemm_f16_t<2><<<ggrid, 256, GT_SMEM>>>((const uint4*)pyA, (const uint4*)pWk,
        nullptr, (unsigned*)pKf, cosb, sinb, M, DM_, DM_);
    gemm_f16_t<3><<<ggrid, 256, GT_SMEM>>>((const uint4*)pyA, (const uint4*)pWv,
        nullptr, (unsigned*)pVf, nullptr, nullptr, M, DM_, DM_);

    attn_f16<<<dim3(T_ / 128, H_, B_), 256, AT_SMEM>>>(
        (const uint4*)pQf, (const uint4*)pKf, (const uint4*)pVf,
        mask, (const int*)pfl, (unsigned*)poA);

    gemm_f16_t<0><<<ggrid, 256, GT_SMEM>>>((const uint4*)poA, (const uint4*)pWo,
        out, nullptr, nullptr, nullptr, M, DM_, DM_);
}

// round 7
// speedup vs baseline: 7.4607x; 1.0221x over previous
#include <cuda_runtime.h>
#include <cuda_fp16.h>
#include <cstdint>

#define B_  2
#define T_  2048
#define S_  2048
#define H_  16
#define HD_ 64
#define DM_ 1024

// Scratch (allocation-free rule: __device__ globals)
__device__ unsigned g_xA[B_*T_*DM_/2];
__device__ unsigned g_yA[B_*S_*DM_/2];
__device__ unsigned g_oA[B_*T_*DM_/2];
__device__ unsigned g_WqB[DM_*DM_/2];
__device__ unsigned g_WkB[DM_*DM_/2];
__device__ unsigned g_WvB[DM_*DM_/2];
__device__ unsigned g_WoB[DM_*DM_/2];
__device__ unsigned g_Qf[2*1024*1024];
__device__ unsigned g_Kf[2*1024*1024];
__device__ unsigned g_Vf[2*1024*1024];
__device__ int      g_flags[1024];

// ---------------------------------------------------------------------------
// helpers
// ---------------------------------------------------------------------------
__device__ __forceinline__ unsigned packh2(float a, float b) {
    __half2 h = __floats2half2_rn(a, b);
    return *(unsigned*)&h;
}

__device__ __forceinline__ void mma16(float c[4], const unsigned a[4], const unsigned b[2]) {
    asm volatile(
        "mma.sync.aligned.m16n8k16.row.col.f32.f16.f16.f32 "
        "{%0,%1,%2,%3}, {%4,%5,%6,%7}, {%8,%9}, {%0,%1,%2,%3};"
        : "+f"(c[0]), "+f"(c[1]), "+f"(c[2]), "+f"(c[3])
        : "r"(a[0]), "r"(a[1]), "r"(a[2]), "r"(a[3]), "r"(b[0]), "r"(b[1]));
}

__device__ __forceinline__ uint32_t smem_u32(const void* p) {
    uint32_t a;
    asm("{ .reg .u64 t; cvta.to.shared.u64 t, %1; cvt.u32.u64 %0, t; }" : "=r"(a) : "l"(p));
    return a;
}

#define CP_ASYNC16(dst, src) \
    asm volatile("cp.async.cg.shared.global [%0], [%1], 16;" :: "r"(dst), "l"(src) : "memory")
#define CP_COMMIT() asm volatile("cp.async.commit_group;" ::: "memory")
#define CP_WAIT1()  asm volatile("cp.async.wait_group 1;" ::: "memory")
#define CP_WAIT0()  asm volatile("cp.async.wait_group 0;" ::: "memory")

// ---------------------------------------------------------------------------
// ONE fused prep kernel: convA(x), convA(y), convB(Wq/Wk/Wv/Wo), maskflags.
// Block ranges:
//   [0,8192)      convA x     [8192,16384)  convA y
//   [16384,24576) convB (Wq|Wk|Wv|Wo, 2048 blocks each)
//   [24576,25600) maskflags
// ---------------------------------------------------------------------------
__global__ __launch_bounds__(256)
void prep_kernel(const float* __restrict__ x,  const float* __restrict__ y,
                 const float* __restrict__ Wq, const float* __restrict__ Wk,
                 const float* __restrict__ Wv, const float* __restrict__ Wo,
                 const float* __restrict__ mask,
                 unsigned* __restrict__ xA, unsigned* __restrict__ yA,
                 unsigned* __restrict__ WqB, unsigned* __restrict__ WkB,
                 unsigned* __restrict__ WvB, unsigned* __restrict__ WoB,
                 int* __restrict__ flags) {
    const int blk = blockIdx.x;
    const int tid = threadIdx.x;

    if (blk < 16384) {
        // convA: fp32 [4096 x 1024] -> fp16 A-fragment order
        const float* src = (blk < 8192) ? x  : y;
        unsigned*    dst = (blk < 8192) ? xA : yA;
        size_t idx = (size_t)(blk & 8191) * 256 + tid;
        int row = (int)(idx >> 9);
        int c   = (int)(idx & 511) << 1;
        float2 v = *(const float2*)&src[(size_t)row * 1024 + c];
        int mt = row >> 4, rr = row & 15, g = rr & 7, hr = rr >> 3;
        int kt = c >> 4, cc = c & 15, tig = (cc >> 1) & 3, hc = cc >> 3;
        dst[((size_t)(mt * 64 + kt) << 7) + ((g * 4 + tig) << 2) + hr + 2 * hc] =
            packh2(v.x, v.y);
    } else if (blk < 24576) {
        // convB: W fp32 [1024 x 1024] -> fp16 B-fragment order
        int r = blk - 16384;
        int w = r >> 11;
        const float* W   = (w == 0) ? Wq  : (w == 1) ? Wk  : (w == 2) ? Wv  : Wo;
        unsigned*    dst = (w == 0) ? WqB : (w == 1) ? WkB : (w == 2) ? WvB : WoB;
        size_t idx = (size_t)(r & 2047) * 256 + tid;
        int n = (int)(idx & 1023);
        int k = (int)(idx >> 10) << 1;
        float lo = W[(size_t)k * 1024 + n];
        float hi = W[(size_t)(k + 1) * 1024 + n];
        int kt = k >> 4, kk = k & 15, hb = kk >> 3, tig = (kk & 7) >> 1;
        int nt = n >> 3, g = n & 7;
        dst[((size_t)(kt * 128 + nt) << 6) + ((g * 4 + tig) << 1) + hb] = packh2(lo, hi);
    } else {
        // maskflags: per-(b, tblock128, sblock64) nonzero flags
        int id = blk - 24576;
        int sb = id & 31, tb = (id >> 5) & 15, b = id >> 9;
        const float* mb = mask + ((size_t)(b * 2048 + tb * 128)) * 2048 + sb * 64;
        int nz = 0;
        int row0 = tid >> 4;
        int c4   = (tid & 15) << 2;
        #pragma unroll
        for (int r2 = 0; r2 < 8; r2++) {
            float4 v = *(const float4*)&mb[(size_t)(row0 + r2 * 16) * 2048 + c4];
            nz |= (v.x != 0.f) | (v.y != 0.f) | (v.z != 0.f) | (v.w != 0.f);
        }
        nz = __syncthreads_or(nz);
        if (tid == 0) flags[(b * 16 + tb) * 32 + sb] = nz;
    }
}

// ---------------------------------------------------------------------------
// Merged Q/K/V projection GEMM. Grid (24, 32): op = bx>>3 selects operands
// and epilogue (0: rope+scale->Qf, 1: rope->Kf, 2: V-frags->Vf).
// 128x128x32 tile, 3-stage cp.async, K=N=1024 hardcoded.
// ---------------------------------------------------------------------------
#define GT_SMEM 49152

__global__ __launch_bounds__(256, 2)
void gemm_qkv(const uint4* __restrict__ xA, const uint4* __restrict__ yA,
              const uint4* __restrict__ WqB, const uint4* __restrict__ WkB,
              const uint4* __restrict__ WvB,
              unsigned* __restrict__ Qf, unsigned* __restrict__ Kf,
              unsigned* __restrict__ Vf,
              const float* __restrict__ cosb, const float* __restrict__ sinb) {
    extern __shared__ unsigned sm16[];
    const uint32_t sb = smem_u32(sm16);
    const int op = blockIdx.x >> 3;
    const uint4* Af = (op == 0) ? xA : yA;
    const uint4* Bf = (op == 0) ? WqB : (op == 1) ? WkB : WvB;
    unsigned* Fout  = (op == 0) ? Qf  : (op == 1) ? Kf  : Vf;

    const int tid  = threadIdx.x;
    const int lane = tid & 31;
    const int wid  = tid >> 5;
    const int warp_m = wid >> 2;
    const int warp_n = wid & 3;
    const int g   = lane >> 2;
    const int tig = lane & 3;
    const int bm = blockIdx.y * 128;
    const int bn = (blockIdx.x & 7) * 128;

    float acc[4][4][4];
    #pragma unroll
    for (int i = 0; i < 4; i++)
        #pragma unroll
        for (int j = 0; j < 4; j++)
            #pragma unroll
            for (int r = 0; r < 4; r++) acc[i][j][r] = 0.f;

    auto issue = [&](int kb, int buf) {
        #pragma unroll
        for (int u = 0; u < 2; u++) {
            int i = tid + u * 256;
            int ti = i >> 5, mt = ti >> 1, kt = ti & 1;
            size_t gt = (size_t)((bm >> 4) + mt) * 64 + kb * 2 + kt;
            CP_ASYNC16(sb + (buf * 4096 + ti * 128 + (i & 31) * 4) * 4,
                       Af + gt * 32 + (i & 31));
            int tj = i >> 4, bkt = tj >> 4, nt = tj & 15;
            size_t gtb = (size_t)(kb * 2 + bkt) * 128 + (bn >> 3) + nt;
            CP_ASYNC16(sb + (buf * 4096 + 2048 + tj * 64 + (i & 15) * 4) * 4,
                       Bf + gtb * 16 + (i & 15));
        }
        CP_COMMIT();
    };

    issue(0, 0);
    issue(1, 1);

    for (int kb = 0; kb < 32; kb++) {
        if (kb + 2 < 32) { CP_WAIT1(); } else { CP_WAIT0(); }
        __syncthreads();
        if (kb + 2 < 32) issue(kb + 2, (kb + 2) % 3);

        const int buf = kb % 3;
        const unsigned* aw = sm16 + buf * 4096;
        const unsigned* bw = aw + 2048;
        #pragma unroll
        for (int kt = 0; kt < 2; kt++) {
            unsigned a[4][4], b[4][2];
            #pragma unroll
            for (int im = 0; im < 4; im++)
                *(uint4*)a[im] = *(const uint4*)&aw[(((warp_m * 4 + im) * 2 + kt) << 7) + lane * 4];
            #pragma unroll
            for (int in_ = 0; in_ < 4; in_++)
                *(uint2*)b[in_] = *(const uint2*)&bw[((kt * 16 + warp_n * 4 + in_) << 6) + lane * 2];
            #pragma unroll
            for (int im = 0; im < 4; im++)
                #pragma unroll
                for (int in_ = 0; in_ < 4; in_++)
                    mma16(acc[im][in_], a[im], b[in_]);
        }
        __syncthreads();
    }

    if (op == 2) {
        // V: output row = s, col = h*64+d. Pair (s even, s odd) via shfl_xor 4.
        #pragma unroll
        for (int im = 0; im < 4; im++) {
            int row = bm + warp_m * 64 + im * 16;
            int b = row >> 11;
            int s = row & 2047;
            int kt = s >> 4;
            #pragma unroll
            for (int in_ = 0; in_ < 4; in_++) {
                #pragma unroll
                for (int e = 0; e < 2; e++) {
                    float v0 = acc[im][in_][e];
                    float v1 = acc[im][in_][2 + e];
                    float p0 = __shfl_xor_sync(0xffffffffu, v0, 4);
                    float p1 = __shfl_xor_sync(0xffffffffu, v1, 4);
                    if ((g & 1) == 0) {
                        int cc = bn + warp_n * 32 + in_ * 8 + tig * 2 + e;
                        int h = (cc >> 6) & 15, d = cc & 63;
                        int nt = d >> 3, dg = d & 7;
                        int bh = b * 16 + h;
                        size_t base = (size_t)bh * 65536 + ((size_t)kt << 9) +
                                      (nt << 6) + ((dg * 4 + (g >> 1)) << 1);
                        Fout[base]     = packh2(v0, p0);
                        Fout[base + 1] = packh2(v1, p1);
                    }
                }
            }
        }
    } else {
        const float QS = (op == 0) ? 0.125f : 1.0f;
        #pragma unroll
        for (int im = 0; im < 4; im++) {
            int row = bm + warp_m * 64 + im * 16 + g;
            int b = row >> 11, t = row & 2047;
            float v[4][4];
            #pragma unroll
            for (int j = 0; j < 4; j++)
                #pragma unroll
                for (int r = 0; r < 4; r++) v[j][r] = acc[im][j][r];
            if ((warp_n & 1) == 0) {   // d in [0,32): partial rope
                #pragma unroll
                for (int in0 = 0; in0 < 2; in0++) {
                    #pragma unroll
                    for (int e = 0; e < 2; e++) {
                        int d = in0 * 8 + tig * 2 + e;
                        float cl = cosb[t * 16 + d],       sl = sinb[t * 16 + d];
                        float ch = cosb[(t + 8) * 16 + d], sh = sinb[(t + 8) * 16 + d];
                        float x1 = v[in0][e],     x2 = v[in0 + 2][e];
                        v[in0][e]       = x1 * cl - x2 * sl;
                        v[in0 + 2][e]   = x2 * cl + x1 * sl;
                        float y1 = v[in0][2 + e], y2 = v[in0 + 2][2 + e];
                        v[in0][2 + e]     = y1 * ch - y2 * sh;
                        v[in0 + 2][2 + e] = y2 * ch + y1 * sh;
                    }
                }
            }
            #pragma unroll
            for (int p = 0; p < 2; p++) {
                int in0 = 2 * p, in1 = 2 * p + 1;
                int cc = bn + warp_n * 32 + in0 * 8;
                int h = (cc >> 6) & 15, d = cc & 63, kt = d >> 4;
                int bh = b * 16 + h;
                if (op == 0) {
                    int mt = t >> 4;
                    uint4 w;
                    w.x = packh2(v[in0][0] * QS, v[in0][1] * QS);
                    w.y = packh2(v[in0][2] * QS, v[in0][3] * QS);
                    w.z = packh2(v[in1][0] * QS, v[in1][1] * QS);
                    w.w = packh2(v[in1][2] * QS, v[in1][3] * QS);
                    *(uint4*)&Fout[(size_t)bh * 65536 + ((size_t)(mt * 4 + kt) << 7) + lane * 4] = w;
                } else {
                    int nt = t >> 3;
                    size_t base = (size_t)bh * 65536 + ((size_t)nt << 8) + (kt << 6) + (g * 4 + tig) * 2;
                    *(uint2*)&Fout[base] =
                        make_uint2(packh2(v[in0][0], v[in0][1]), packh2(v[in1][0], v[in1][1]));
                    *(uint2*)&Fout[base + 256] =
                        make_uint2(packh2(v[in0][2], v[in0][3]), packh2(v[in1][2], v[in1][3]));
                }
            }
        }
    }
}

// ---------------------------------------------------------------------------
// Output GEMM: oA frags @ WoB frags -> fp32 out.
// ---------------------------------------------------------------------------
__global__ __launch_bounds__(256, 2)
void gemm_out(const uint4* __restrict__ Af, const uint4* __restrict__ Bf,
              float* __restrict__ C) {
    extern __shared__ unsigned sm16[];
    const uint32_t sb = smem_u32(sm16);
    const int tid  = threadIdx.x;
    const int lane = tid & 31;
    const int wid  = tid >> 5;
    const int warp_m = wid >> 2;
    const int warp_n = wid & 3;
    const int g   = lane >> 2;
    const int tig = lane & 3;
    const int bm = blockIdx.y * 128;
    const int bn = blockIdx.x * 128;

    float acc[4][4][4];
    #pragma unroll
    for (int i = 0; i < 4; i++)
        #pragma unroll
        for (int j = 0; j < 4; j++)
            #pragma unroll
            for (int r = 0; r < 4; r++) acc[i][j][r] = 0.f;

    auto issue = [&](int kb, int buf) {
        #pragma unroll
        for (int u = 0; u < 2; u++) {
            int i = tid + u * 256;
            int ti = i >> 5, mt = ti >> 1, kt = ti & 1;
            size_t gt = (size_t)((bm >> 4) + mt) * 64 + kb * 2 + kt;
            CP_ASYNC16(sb + (buf * 4096 + ti * 128 + (i & 31) * 4) * 4,
                       Af + gt * 32 + (i & 31));
            int tj = i >> 4, bkt = tj >> 4, nt = tj & 15;
            size_t gtb = (size_t)(kb * 2 + bkt) * 128 + (bn >> 3) + nt;
            CP_ASYNC16(sb + (buf * 4096 + 2048 + tj * 64 + (i & 15) * 4) * 4,
                       Bf + gtb * 16 + (i & 15));
        }
        CP_COMMIT();
    };

    issue(0, 0);
    issue(1, 1);

    for (int kb = 0; kb < 32; kb++) {
        if (kb + 2 < 32) { CP_WAIT1(); } else { CP_WAIT0(); }
        __syncthreads();
        if (kb + 2 < 32) issue(kb + 2, (kb + 2) % 3);

        const int buf = kb % 3;
        const unsigned* aw = sm16 + buf * 4096;
        const unsigned* bw = aw + 2048;
        #pragma unroll
        for (int kt = 0; kt < 2; kt++) {
            unsigned a[4][4], b[4][2];
            #pragma unroll
            for (int im = 0; im < 4; im++)
                *(uint4*)a[im] = *(const uint4*)&aw[(((warp_m * 4 + im) * 2 + kt) << 7) + lane * 4];
            #pragma unroll
            for (int in_ = 0; in_ < 4; in_++)
                *(uint2*)b[in_] = *(const uint2*)&bw[((kt * 16 + warp_n * 4 + in_) << 6) + lane * 2];
            #pragma unroll
            for (int im = 0; im < 4; im++)
                #pragma unroll
                for (int in_ = 0; in_ < 4; in_++)
                    mma16(acc[im][in_], a[im], b[in_]);
        }
        __syncthreads();
    }

    #pragma unroll
    for (int im = 0; im < 4; im++) {
        int r0 = bm + warp_m * 64 + im * 16 + g;
        #pragma unroll
        for (int in_ = 0; in_ < 4; in_++) {
            int cc = bn + warp_n * 32 + in_ * 8 + tig * 2;
            *(float2*)&C[(size_t)r0 * 1024 + cc]       = make_float2(acc[im][in_][0], acc[im][in_][1]);
            *(float2*)&C[(size_t)(r0 + 8) * 1024 + cc] = make_float2(acc[im][in_][2], acc[im][in_][3]);
        }
    }
}

// ---------------------------------------------------------------------------
// Fused flash attention: Q and P register-resident, KV double-buffered
// cp.async (32KB smem), mask gated by zero-tile flags, output as A-frags.
// ---------------------------------------------------------------------------
#define AT_SMEM (8192 * 4)

__global__ __launch_bounds__(256, 2)
void attn_f16(const uint4* __restrict__ Qf, const uint4* __restrict__ Kf,
              const uint4* __restrict__ Vf, const float* __restrict__ mask,
              const int* __restrict__ flags, unsigned* __restrict__ Of) {
    extern __shared__ unsigned sma[];
    const uint32_t sb = smem_u32(sma);
    const int tid  = threadIdx.x;
    const int lane = tid & 31;
    const int wid  = tid >> 5;
    const int g    = lane >> 2;
    const int tig  = lane & 3;
    const int tb   = blockIdx.x;
    const int h    = blockIdx.y;
    const int b    = blockIdx.z;
    const int t0   = tb * 128;
    const int bh   = b * 16 + h;

    auto issueKV = [&](int s0, int buf) {
        size_t kb = (size_t)bh * 16384 + (size_t)(s0 >> 3) * 64;
        size_t vb = (size_t)bh * 16384 + (size_t)(s0 >> 4) * 128;
        #pragma unroll
        for (int u = 0; u < 2; u++) {
            int c = tid + u * 256;
            CP_ASYNC16(sb + (buf * 4096 + c * 4) * 4,        Kf + kb + c);
            CP_ASYNC16(sb + (buf * 4096 + 2048 + c * 4) * 4, Vf + vb + c);
        }
    };
    issueKV(0, 0);  CP_COMMIT();
    issueKV(64, 1); CP_COMMIT();

    unsigned qr[4][4];
    {
        int mt = (t0 >> 4) + wid;
        #pragma unroll
        for (int kt = 0; kt < 4; kt++)
            *(uint4*)qr[kt] = Qf[(size_t)bh * 16384 + (size_t)(mt * 4 + kt) * 32 + lane];
    }

    float m_[2] = {-1e30f, -1e30f};
    float l_[2] = {0.f, 0.f};
    float acc[8][4];
    #pragma unroll
    for (int nt = 0; nt < 8; nt++)
        #pragma unroll
        for (int r = 0; r < 4; r++) acc[nt][r] = 0.f;

    const int nT = S_ / 64;
    for (int i = 0; i < nT; i++) {
        if (i + 1 < nT) { CP_WAIT1(); } else { CP_WAIT0(); }
        __syncthreads();
        const int buf = i & 1;
        const unsigned* kw = sma + buf * 4096;
        const unsigned* vw = kw + 2048;

        float sc[8][4];
        int mz = __ldg(&flags[(b * 16 + tb) * 32 + i]);
        if (mz) {
            const float* mr0 = &mask[((size_t)b * T_ + t0 + wid * 16 + g) * S_ + i * 64];
            const float* mr1 = mr0 + 8 * S_;
            #pragma unroll
            for (int nt = 0; nt < 8; nt++) {
                float2 m0 = *(const float2*)&mr0[nt * 8 + 2 * tig];
                float2 m1 = *(const float2*)&mr1[nt * 8 + 2 * tig];
                sc[nt][0] = m0.x; sc[nt][1] = m0.y;
                sc[nt][2] = m1.x; sc[nt][3] = m1.y;
            }
        } else {
            #pragma unroll
            for (int nt = 0; nt < 8; nt++)
                #pragma unroll
                for (int r = 0; r < 4; r++) sc[nt][r] = 0.f;
        }

        #pragma unroll
        for (int kt = 0; kt < 4; kt++) {
            #pragma unroll
            for (int nt = 0; nt < 8; nt++) {
                unsigned bb[2];
                *(uint2*)bb = *(const uint2*)&kw[((nt * 4 + kt) << 6) + lane * 2];
                mma16(sc[nt], qr[kt], bb);
            }
        }

        #pragma unroll
        for (int e = 0; e < 2; e++) {
            float tmax = -1e30f;
            #pragma unroll
            for (int nt = 0; nt < 8; nt++)
                tmax = fmaxf(tmax, fmaxf(sc[nt][2 * e], sc[nt][2 * e + 1]));
            tmax = fmaxf(tmax, __shfl_xor_sync(0xffffffffu, tmax, 1));
            tmax = fmaxf(tmax, __shfl_xor_sync(0xffffffffu, tmax, 2));
            float mnew  = fmaxf(m_[e], tmax);
            float alpha = __expf(m_[e] - mnew);
            m_[e] = mnew;
            float ps = 0.f;
            #pragma unroll
            for (int nt = 0; nt < 8; nt++) {
                float p0 = __expf(sc[nt][2 * e]     - mnew);
                float p1 = __expf(sc[nt][2 * e + 1] - mnew);
                sc[nt][2 * e] = p0; sc[nt][2 * e + 1] = p1;
                ps += p0 + p1;
            }
            ps += __shfl_xor_sync(0xffffffffu, ps, 1);
            ps += __shfl_xor_sync(0xffffffffu, ps, 2);
            l_[e] = l_[e] * alpha + ps;
            #pragma unroll
            for (int nt = 0; nt < 8; nt++) {
                acc[nt][2 * e]     *= alpha;
                acc[nt][2 * e + 1] *= alpha;
            }
        }

        #pragma unroll
        for (int kt = 0; kt < 4; kt++) {
            unsigned a[4];
            a[0] = packh2(sc[2 * kt][0],     sc[2 * kt][1]);
            a[1] = packh2(sc[2 * kt][2],     sc[2 * kt][3]);
            a[2] = packh2(sc[2 * kt + 1][0], sc[2 * kt + 1][1]);
            a[3] = packh2(sc[2 * kt + 1][2], sc[2 * kt + 1][3]);
            #pragma unroll
            for (int nt = 0; nt < 8; nt++) {
                unsigned bb[2];
                *(uint2*)bb = *(const uint2*)&vw[((kt * 8 + nt) << 6) + lane * 2];
                mma16(acc[nt], a, bb);
            }
        }
        __syncthreads();
        if (i + 2 < nT) { issueKV((i + 2) * 64, buf); CP_COMMIT(); }
    }

    float inv0 = 1.f / l_[0];
    float inv1 = 1.f / l_[1];
    int mt_g = (b * 2048 + t0 + wid * 16) >> 4;
    #pragma unroll
    for (int kt = 0; kt < 4; kt++) {
        int nt0 = 2 * kt, nt1 = nt0 + 1;
        uint4 w;
        w.x = packh2(acc[nt0][0] * inv0, acc[nt0][1] * inv0);
        w.y = packh2(acc[nt0][2] * inv1, acc[nt0][3] * inv1);
        w.z = packh2(acc[nt1][0] * inv0, acc[nt1][1] * inv0);
        w.w = packh2(acc[nt1][2] * inv1, acc[nt1][3] * inv1);
        int kt_g = h * 4 + kt;
        *(uint4*)&Of[((size_t)(mt_g * 64 + kt_g) << 7) + lane * 4] = w;
    }
}

// ---------------------------------------------------------------------------
extern "C" void kernel_launch(void* const* d_in, const int* in_sizes, int n_in,
                              void* d_out, int out_size) {
    const float* x    = (const float*)d_in[0];
    const float* y    = (const float*)d_in[1];
    const float* cosb = (const float*)d_in[2];
    const float* sinb = (const float*)d_in[3];
    const float* mask = (const float*)d_in[4];
    const float* Wq   = (const float*)d_in[5];
    const float* Wk   = (const float*)d_in[6];
    const float* Wv   = (const float*)d_in[7];
    const float* Wo   = (const float*)d_in[8];
    float* out = (float*)d_out;

    void *pxA, *pyA, *poA, *pWq, *pWk, *pWv, *pWo, *pQf, *pKf, *pVf, *pfl;
    cudaGetSymbolAddress(&pxA, g_xA);
    cudaGetSymbolAddress(&pyA, g_yA);
    cudaGetSymbolAddress(&poA, g_oA);
    cudaGetSymbolAddress(&pWq, g_WqB);
    cudaGetSymbolAddress(&pWk, g_WkB);
    cudaGetSymbolAddress(&pWv, g_WvB);
    cudaGetSymbolAddress(&pWo, g_WoB);
    cudaGetSymbolAddress(&pQf, g_Qf);
    cudaGetSymbolAddress(&pKf, g_Kf);
    cudaGetSymbolAddress(&pVf, g_Vf);
    cudaGetSymbolAddress(&pfl, g_flags);

    cudaFuncSetAttribute(gemm_qkv, cudaFuncAttributeMaxDynamicSharedMemorySize, GT_SMEM);
    cudaFuncSetAttribute(gemm_out, cudaFuncAttributeMaxDynamicSharedMemorySize, GT_SMEM);
    cudaFuncSetAttribute(attn_f16, cudaFuncAttributeMaxDynamicSharedMemorySize, AT_SMEM);

    prep_kernel<<<25600, 256>>>(x, y, Wq, Wk, Wv, Wo, mask,
                                (unsigned*)pxA, (unsigned*)pyA,
                                (unsigned*)pWq, (unsigned*)pWk,
                                (unsigned*)pWv, (unsigned*)pWo,
                                (int*)pfl);

    gemm_qkv<<<dim3(24, 32), 256, GT_SMEM>>>(
        (const uint4*)pxA, (const uint4*)pyA,
        (const uint4*)pWq, (const uint4*)pWk, (const uint4*)pWv,
        (unsigned*)pQf, (unsigned*)pKf, (unsigned*)pVf, cosb, sinb);

    attn_f16<<<dim3(T_ / 128, H_, B_), 256, AT_SMEM>>>(
        (const uint4*)pQf, (const uint4*)pKf, (const uint4*)pVf,
        mask, (const int*)pfl, (unsigned*)poA);

    gemm_out<<<dim3(8, 32), 256, GT_SMEM>>>(
        (const uint4*)poA, (const uint4*)pWo, out);
}

// round 8
// speedup vs baseline: 7.7451x; 1.0381x over previous
#include <cuda_runtime.h>
#include <cuda_fp16.h>
#include <cstdint>

#define B_  2
#define T_  2048
#define S_  2048
#define H_  16
#define HD_ 64
#define DM_ 1024

// Scratch (allocation-free rule: __device__ globals)
__device__ unsigned g_xA[B_*T_*DM_/2];
__device__ unsigned g_yA[B_*S_*DM_/2];
__device__ unsigned g_oA[B_*T_*DM_/2];
__device__ unsigned g_WqB[DM_*DM_/2];
__device__ unsigned g_WkB[DM_*DM_/2];
__device__ unsigned g_WvB[DM_*DM_/2];
__device__ unsigned g_WoB[DM_*DM_/2];
__device__ unsigned g_Qf[2*1024*1024];
__device__ unsigned g_Kf[2*1024*1024];
__device__ unsigned g_Vf[2*1024*1024];
__device__ int      g_flags[1024];

// ---------------------------------------------------------------------------
// helpers
// ---------------------------------------------------------------------------
__device__ __forceinline__ unsigned packh2(float a, float b) {
    __half2 h = __floats2half2_rn(a, b);
    return *(unsigned*)&h;
}

__device__ __forceinline__ void mma16(float c[4], const unsigned a[4], const unsigned b[2]) {
    asm volatile(
        "mma.sync.aligned.m16n8k16.row.col.f32.f16.f16.f32 "
        "{%0,%1,%2,%3}, {%4,%5,%6,%7}, {%8,%9}, {%0,%1,%2,%3};"
        : "+f"(c[0]), "+f"(c[1]), "+f"(c[2]), "+f"(c[3])
        : "r"(a[0]), "r"(a[1]), "r"(a[2]), "r"(a[3]), "r"(b[0]), "r"(b[1]));
}

__device__ __forceinline__ uint32_t smem_u32(const void* p) {
    uint32_t a;
    asm("{ .reg .u64 t; cvta.to.shared.u64 t, %1; cvt.u32.u64 %0, t; }" : "=r"(a) : "l"(p));
    return a;
}

#define CP_ASYNC16(dst, src) \
    asm volatile("cp.async.cg.shared.global [%0], [%1], 16;" :: "r"(dst), "l"(src) : "memory")
#define CP_COMMIT() asm volatile("cp.async.commit_group;" ::: "memory")
#define CP_WAIT2()  asm volatile("cp.async.wait_group 2;" ::: "memory")
#define CP_WAIT1()  asm volatile("cp.async.wait_group 1;" ::: "memory")
#define CP_WAIT0()  asm volatile("cp.async.wait_group 0;" ::: "memory")

// ---------------------------------------------------------------------------
// ONE fused prep kernel: convA(x), convA(y), convB(Wq/Wk/Wv/Wo), maskflags.
// ---------------------------------------------------------------------------
__global__ __launch_bounds__(256)
void prep_kernel(const float* __restrict__ x,  const float* __restrict__ y,
                 const float* __restrict__ Wq, const float* __restrict__ Wk,
                 const float* __restrict__ Wv, const float* __restrict__ Wo,
                 const float* __restrict__ mask,
                 unsigned* __restrict__ xA, unsigned* __restrict__ yA,
                 unsigned* __restrict__ WqB, unsigned* __restrict__ WkB,
                 unsigned* __restrict__ WvB, unsigned* __restrict__ WoB,
                 int* __restrict__ flags) {
    const int blk = blockIdx.x;
    const int tid = threadIdx.x;

    if (blk < 16384) {
        const float* src = (blk < 8192) ? x  : y;
        unsigned*    dst = (blk < 8192) ? xA : yA;
        size_t idx = (size_t)(blk & 8191) * 256 + tid;
        int row = (int)(idx >> 9);
        int c   = (int)(idx & 511) << 1;
        float2 v = *(const float2*)&src[(size_t)row * 1024 + c];
        int mt = row >> 4, rr = row & 15, g = rr & 7, hr = rr >> 3;
        int kt = c >> 4, cc = c & 15, tig = (cc >> 1) & 3, hc = cc >> 3;
        dst[((size_t)(mt * 64 + kt) << 7) + ((g * 4 + tig) << 2) + hr + 2 * hc] =
            packh2(v.x, v.y);
    } else if (blk < 24576) {
        int r = blk - 16384;
        int w = r >> 11;
        const float* W   = (w == 0) ? Wq  : (w == 1) ? Wk  : (w == 2) ? Wv  : Wo;
        unsigned*    dst = (w == 0) ? WqB : (w == 1) ? WkB : (w == 2) ? WvB : WoB;
        size_t idx = (size_t)(r & 2047) * 256 + tid;
        int n = (int)(idx & 1023);
        int k = (int)(idx >> 10) << 1;
        float lo = W[(size_t)k * 1024 + n];
        float hi = W[(size_t)(k + 1) * 1024 + n];
        int kt = k >> 4, kk = k & 15, hb = kk >> 3, tig = (kk & 7) >> 1;
        int nt = n >> 3, g = n & 7;
        dst[((size_t)(kt * 128 + nt) << 6) + ((g * 4 + tig) << 1) + hb] = packh2(lo, hi);
    } else {
        int id = blk - 24576;
        int sb = id & 31, tb = (id >> 5) & 15, b = id >> 9;
        const float* mb = mask + ((size_t)(b * 2048 + tb * 128)) * 2048 + sb * 64;
        int nz = 0;
        int row0 = tid >> 4;
        int c4   = (tid & 15) << 2;
        #pragma unroll
        for (int r2 = 0; r2 < 8; r2++) {
            float4 v = *(const float4*)&mb[(size_t)(row0 + r2 * 16) * 2048 + c4];
            nz |= (v.x != 0.f) | (v.y != 0.f) | (v.z != 0.f) | (v.w != 0.f);
        }
        nz = __syncthreads_or(nz);
        if (tid == 0) flags[(b * 16 + tb) * 32 + sb] = nz;
    }
}

// ---------------------------------------------------------------------------
// GEMM mainloop (shared by qkv + out): 128x128x32 tile, 4-stage cp.async,
// ONE barrier per k-iteration.
// smem: 4 buffers x 4096 u32 (A 2048 + B 2048) = 64KB
// ---------------------------------------------------------------------------
#define GT_SMEM 65536

#define GEMM_MAINLOOP(Af, Bf)                                                   \
    float acc[4][4][4];                                                         \
    _Pragma("unroll")                                                           \
    for (int i = 0; i < 4; i++)                                                 \
        _Pragma("unroll")                                                       \
        for (int j = 0; j < 4; j++)                                             \
            _Pragma("unroll")                                                   \
            for (int r = 0; r < 4; r++) acc[i][j][r] = 0.f;                     \
    auto issue = [&](int kb, int buf) {                                         \
        _Pragma("unroll")                                                       \
        for (int u = 0; u < 2; u++) {                                           \
            int i = tid + u * 256;                                              \
            int ti = i >> 5, mt = ti >> 1, kt = ti & 1;                         \
            size_t gt = (size_t)((bm >> 4) + mt) * 64 + kb * 2 + kt;            \
            CP_ASYNC16(sb + (buf * 4096 + ti * 128 + (i & 31) * 4) * 4,         \
                       (Af) + gt * 32 + (i & 31));                              \
            int tj = i >> 4, bkt = tj >> 4, nt = tj & 15;                       \
            size_t gtb = (size_t)(kb * 2 + bkt) * 128 + (bn >> 3) + nt;         \
            CP_ASYNC16(sb + (buf * 4096 + 2048 + tj * 64 + (i & 15) * 4) * 4,   \
                       (Bf) + gtb * 16 + (i & 15));                             \
        }                                                                       \
        CP_COMMIT();                                                            \
    };                                                                          \
    issue(0, 0); issue(1, 1); issue(2, 2);                                      \
    for (int kb = 0; kb < 32; kb++) {                                           \
        if (kb < 30) { CP_WAIT2(); } else if (kb == 30) { CP_WAIT1(); }         \
        else { CP_WAIT0(); }                                                    \
        __syncthreads();                                                        \
        if (kb + 3 < 32) issue(kb + 3, (kb + 3) & 3);                           \
        const unsigned* aw = sm16 + (kb & 3) * 4096;                            \
        const unsigned* bw = aw + 2048;                                         \
        _Pragma("unroll")                                                       \
        for (int kt = 0; kt < 2; kt++) {                                        \
            unsigned a[4][4], b[4][2];                                          \
            _Pragma("unroll")                                                   \
            for (int im = 0; im < 4; im++)                                      \
                *(uint4*)a[im] = *(const uint4*)&aw[(((warp_m * 4 + im) * 2 + kt) << 7) + lane * 4]; \
            _Pragma("unroll")                                                   \
            for (int in_ = 0; in_ < 4; in_++)                                   \
                *(uint2*)b[in_] = *(const uint2*)&bw[((kt * 16 + warp_n * 4 + in_) << 6) + lane * 2]; \
            _Pragma("unroll")                                                   \
            for (int im = 0; im < 4; im++)                                      \
                _Pragma("unroll")                                               \
                for (int in_ = 0; in_ < 4; in_++)                               \
                    mma16(acc[im][in_], a[im], b[in_]);                         \
        }                                                                       \
    }

// ---------------------------------------------------------------------------
// Merged Q/K/V projection GEMM. Grid (24, 32): op = bx>>3.
// ---------------------------------------------------------------------------
__global__ __launch_bounds__(256, 2)
void gemm_qkv(const uint4* __restrict__ xA, const uint4* __restrict__ yA,
              const uint4* __restrict__ WqB, const uint4* __restrict__ WkB,
              const uint4* __restrict__ WvB,
              unsigned* __restrict__ Qf, unsigned* __restrict__ Kf,
              unsigned* __restrict__ Vf,
              const float* __restrict__ cosb, const float* __restrict__ sinb) {
    extern __shared__ unsigned sm16[];
    const uint32_t sb = smem_u32(sm16);
    const int op = blockIdx.x >> 3;
    const uint4* Af = (op == 0) ? xA : yA;
    const uint4* Bf = (op == 0) ? WqB : (op == 1) ? WkB : WvB;
    unsigned* Fout  = (op == 0) ? Qf  : (op == 1) ? Kf  : Vf;

    const int tid  = threadIdx.x;
    const int lane = tid & 31;
    const int wid  = tid >> 5;
    const int warp_m = wid >> 2;
    const int warp_n = wid & 3;
    const int g   = lane >> 2;
    const int tig = lane & 3;
    const int bm = blockIdx.y * 128;
    const int bn = (blockIdx.x & 7) * 128;

    GEMM_MAINLOOP(Af, Bf)

    if (op == 2) {
        // V: output row = s, col = h*64+d. Pair (s even, s odd) via shfl_xor 4.
        #pragma unroll
        for (int im = 0; im < 4; im++) {
            int row = bm + warp_m * 64 + im * 16;
            int b = row >> 11;
            int s = row & 2047;
            int kt = s >> 4;
            #pragma unroll
            for (int in_ = 0; in_ < 4; in_++) {
                #pragma unroll
                for (int e = 0; e < 2; e++) {
                    float v0 = acc[im][in_][e];
                    float v1 = acc[im][in_][2 + e];
                    float p0 = __shfl_xor_sync(0xffffffffu, v0, 4);
                    float p1 = __shfl_xor_sync(0xffffffffu, v1, 4);
                    if ((g & 1) == 0) {
                        int cc = bn + warp_n * 32 + in_ * 8 + tig * 2 + e;
                        int h = (cc >> 6) & 15, d = cc & 63;
                        int nt = d >> 3, dg = d & 7;
                        int bh = b * 16 + h;
                        size_t base = (size_t)bh * 65536 + ((size_t)kt << 9) +
                                      (nt << 6) + ((dg * 4 + (g >> 1)) << 1);
                        Fout[base]     = packh2(v0, p0);
                        Fout[base + 1] = packh2(v1, p1);
                    }
                }
            }
        }
    } else {
        const float QS = (op == 0) ? 0.125f : 1.0f;
        #pragma unroll
        for (int im = 0; im < 4; im++) {
            int row = bm + warp_m * 64 + im * 16 + g;
            int b = row >> 11, t = row & 2047;
            float v[4][4];
            #pragma unroll
            for (int j = 0; j < 4; j++)
                #pragma unroll
                for (int r = 0; r < 4; r++) v[j][r] = acc[im][j][r];
            if ((warp_n & 1) == 0) {   // d in [0,32): partial rope
                #pragma unroll
                for (int in0 = 0; in0 < 2; in0++) {
                    #pragma unroll
                    for (int e = 0; e < 2; e++) {
                        int d = in0 * 8 + tig * 2 + e;
                        float cl = cosb[t * 16 + d],       sl = sinb[t * 16 + d];
                        float ch = cosb[(t + 8) * 16 + d], sh = sinb[(t + 8) * 16 + d];
                        float x1 = v[in0][e],     x2 = v[in0 + 2][e];
                        v[in0][e]       = x1 * cl - x2 * sl;
                        v[in0 + 2][e]   = x2 * cl + x1 * sl;
                        float y1 = v[in0][2 + e], y2 = v[in0 + 2][2 + e];
                        v[in0][2 + e]     = y1 * ch - y2 * sh;
                        v[in0 + 2][2 + e] = y2 * ch + y1 * sh;
                    }
                }
            }
            #pragma unroll
            for (int p = 0; p < 2; p++) {
                int in0 = 2 * p, in1 = 2 * p + 1;
                int cc = bn + warp_n * 32 + in0 * 8;
                int h = (cc >> 6) & 15, d = cc & 63, kt = d >> 4;
                int bh = b * 16 + h;
                if (op == 0) {
                    int mt = t >> 4;
                    uint4 w;
                    w.x = packh2(v[in0][0] * QS, v[in0][1] * QS);
                    w.y = packh2(v[in0][2] * QS, v[in0][3] * QS);
                    w.z = packh2(v[in1][0] * QS, v[in1][1] * QS);
                    w.w = packh2(v[in1][2] * QS, v[in1][3] * QS);
                    *(uint4*)&Fout[(size_t)bh * 65536 + ((size_t)(mt * 4 + kt) << 7) + lane * 4] = w;
                } else {
                    int nt = t >> 3;
                    size_t base = (size_t)bh * 65536 + ((size_t)nt << 8) + (kt << 6) + (g * 4 + tig) * 2;
                    *(uint2*)&Fout[base] =
                        make_uint2(packh2(v[in0][0], v[in0][1]), packh2(v[in1][0], v[in1][1]));
                    *(uint2*)&Fout[base + 256] =
                        make_uint2(packh2(v[in0][2], v[in0][3]), packh2(v[in1][2], v[in1][3]));
                }
            }
        }
    }
}

// ---------------------------------------------------------------------------
// Output GEMM: oA frags @ WoB frags -> fp32 out.
// ---------------------------------------------------------------------------
__global__ __launch_bounds__(256, 2)
void gemm_out(const uint4* __restrict__ Af, const uint4* __restrict__ Bf,
              float* __restrict__ C) {
    extern __shared__ unsigned sm16[];
    const uint32_t sb = smem_u32(sm16);
    const int tid  = threadIdx.x;
    const int lane = tid & 31;
    const int wid  = tid >> 5;
    const int warp_m = wid >> 2;
    const int warp_n = wid & 3;
    const int g   = lane >> 2;
    const int tig = lane & 3;
    const int bm = blockIdx.y * 128;
    const int bn = blockIdx.x * 128;

    GEMM_MAINLOOP(Af, Bf)

    #pragma unroll
    for (int im = 0; im < 4; im++) {
        int r0 = bm + warp_m * 64 + im * 16 + g;
        #pragma unroll
        for (int in_ = 0; in_ < 4; in_++) {
            int cc = bn + warp_n * 32 + in_ * 8 + tig * 2;
            *(float2*)&C[(size_t)r0 * 1024 + cc]       = make_float2(acc[im][in_][0], acc[im][in_][1]);
            *(float2*)&C[(size_t)(r0 + 8) * 1024 + cc] = make_float2(acc[im][in_][2], acc[im][in_][3]);
        }
    }
}

// ---------------------------------------------------------------------------
// Fused flash attention: Q/P register-resident, KV triple-buffered cp.async
// (48KB smem), ONE barrier per tile, mask gated by zero-tile flags,
// output as A-frags.
// ---------------------------------------------------------------------------
#define AT_SMEM (12288 * 4)

__global__ __launch_bounds__(256, 2)
void attn_f16(const uint4* __restrict__ Qf, const uint4* __restrict__ Kf,
              const uint4* __restrict__ Vf, const float* __restrict__ mask,
              const int* __restrict__ flags, unsigned* __restrict__ Of) {
    extern __shared__ unsigned sma[];
    const uint32_t sb = smem_u32(sma);
    const int tid  = threadIdx.x;
    const int lane = tid & 31;
    const int wid  = tid >> 5;
    const int g    = lane >> 2;
    const int tig  = lane & 3;
    const int tb   = blockIdx.x;
    const int h    = blockIdx.y;
    const int b    = blockIdx.z;
    const int t0   = tb * 128;
    const int bh   = b * 16 + h;

    auto issueKV = [&](int s0, int buf) {
        size_t kb = (size_t)bh * 16384 + (size_t)(s0 >> 3) * 64;
        size_t vb = (size_t)bh * 16384 + (size_t)(s0 >> 4) * 128;
        #pragma unroll
        for (int u = 0; u < 2; u++) {
            int c = tid + u * 256;
            CP_ASYNC16(sb + (buf * 4096 + c * 4) * 4,        Kf + kb + c);
            CP_ASYNC16(sb + (buf * 4096 + 2048 + c * 4) * 4, Vf + vb + c);
        }
        CP_COMMIT();
    };
    issueKV(0, 0);
    issueKV(64, 1);

    unsigned qr[4][4];
    {
        int mt = (t0 >> 4) + wid;
        #pragma unroll
        for (int kt = 0; kt < 4; kt++)
            *(uint4*)qr[kt] = Qf[(size_t)bh * 16384 + (size_t)(mt * 4 + kt) * 32 + lane];
    }

    float m_[2] = {-1e30f, -1e30f};
    float l_[2] = {0.f, 0.f};
    float acc[8][4];
    #pragma unroll
    for (int nt = 0; nt < 8; nt++)
        #pragma unroll
        for (int r = 0; r < 4; r++) acc[nt][r] = 0.f;

    const int nT = S_ / 64;   // 32
    int bufc = 0;             // buffer of current tile (mod 3)
    for (int i = 0; i < nT; i++) {
        if (i + 1 < nT) { CP_WAIT1(); } else { CP_WAIT0(); }
        __syncthreads();
        if (i + 2 < nT) {
            int nb = bufc + 2; if (nb >= 3) nb -= 3;
            issueKV((i + 2) * 64, nb);
        }
        const unsigned* kw = sma + bufc * 4096;
        const unsigned* vw = kw + 2048;

        float sc[8][4];
        int mz = __ldg(&flags[(b * 16 + tb) * 32 + i]);
        if (mz) {
            const float* mr0 = &mask[((size_t)b * T_ + t0 + wid * 16 + g) * S_ + i * 64];
            const float* mr1 = mr0 + 8 * S_;
            #pragma unroll
            for (int nt = 0; nt < 8; nt++) {
                float2 m0 = *(const float2*)&mr0[nt * 8 + 2 * tig];
                float2 m1 = *(const float2*)&mr1[nt * 8 + 2 * tig];
                sc[nt][0] = m0.x; sc[nt][1] = m0.y;
                sc[nt][2] = m1.x; sc[nt][3] = m1.y;
            }
        } else {
            #pragma unroll
            for (int nt = 0; nt < 8; nt++)
                #pragma unroll
                for (int r = 0; r < 4; r++) sc[nt][r] = 0.f;
        }

        #pragma unroll
        for (int kt = 0; kt < 4; kt++) {
            #pragma unroll
            for (int nt = 0; nt < 8; nt++) {
                unsigned bb[2];
                *(uint2*)bb = *(const uint2*)&kw[((nt * 4 + kt) << 6) + lane * 2];
                mma16(sc[nt], qr[kt], bb);
            }
        }

        #pragma unroll
        for (int e = 0; e < 2; e++) {
            float tmax = -1e30f;
            #pragma unroll
            for (int nt = 0; nt < 8; nt++)
                tmax = fmaxf(tmax, fmaxf(sc[nt][2 * e], sc[nt][2 * e + 1]));
            tmax = fmaxf(tmax, __shfl_xor_sync(0xffffffffu, tmax, 1));
            tmax = fmaxf(tmax, __shfl_xor_sync(0xffffffffu, tmax, 2));
            float mnew  = fmaxf(m_[e], tmax);
            float alpha = __expf(m_[e] - mnew);
            m_[e] = mnew;
            float ps = 0.f;
            #pragma unroll
            for (int nt = 0; nt < 8; nt++) {
                float p0 = __expf(sc[nt][2 * e]     - mnew);
                float p1 = __expf(sc[nt][2 * e + 1] - mnew);
                sc[nt][2 * e] = p0; sc[nt][2 * e + 1] = p1;
                ps += p0 + p1;
            }
            ps += __shfl_xor_sync(0xffffffffu, ps, 1);
            ps += __shfl_xor_sync(0xffffffffu, ps, 2);
            l_[e] = l_[e] * alpha + ps;
            #pragma unroll
            for (int nt = 0; nt < 8; nt++) {
                acc[nt][2 * e]     *= alpha;
                acc[nt][2 * e + 1] *= alpha;
            }
        }

        #pragma unroll
        for (int kt = 0; kt < 4; kt++) {
            unsigned a[4];
            a[0] = packh2(sc[2 * kt][0],     sc[2 * kt][1]);
            a[1] = packh2(sc[2 * kt][2],     sc[2 * kt][3]);
            a[2] = packh2(sc[2 * kt + 1][0], sc[2 * kt + 1][1]);
            a[3] = packh2(sc[2 * kt + 1][2], sc[2 * kt + 1][3]);
            #pragma unroll
            for (int nt = 0; nt < 8; nt++) {
                unsigned bb[2];
                *(uint2*)bb = *(const uint2*)&vw[((kt * 8 + nt) << 6) + lane * 2];
                mma16(acc[nt], a, bb);
            }
        }
        bufc++; if (bufc >= 3) bufc = 0;
    }

    float inv0 = 1.f / l_[0];
    float inv1 = 1.f / l_[1];
    int mt_g = (b * 2048 + t0 + wid * 16) >> 4;
    #pragma unroll
    for (int kt = 0; kt < 4; kt++) {
        int nt0 = 2 * kt, nt1 = nt0 + 1;
        uint4 w;
        w.x = packh2(acc[nt0][0] * inv0, acc[nt0][1] * inv0);
        w.y = packh2(acc[nt0][2] * inv1, acc[nt0][3] * inv1);
        w.z = packh2(acc[nt1][0] * inv0, acc[nt1][1] * inv0);
        w.w = packh2(acc[nt1][2] * inv1, acc[nt1][3] * inv1);
        int kt_g = h * 4 + kt;
        *(uint4*)&Of[((size_t)(mt_g * 64 + kt_g) << 7) + lane * 4] = w;
    }
}

// ---------------------------------------------------------------------------
extern "C" void kernel_launch(void* const* d_in, const int* in_sizes, int n_in,
                              void* d_out, int out_size) {
    const float* x    = (const float*)d_in[0];
    const float* y    = (const float*)d_in[1];
    const float* cosb = (const float*)d_in[2];
    const float* sinb = (const float*)d_in[3];
    const float* mask = (const float*)d_in[4];
    const float* Wq   = (const float*)d_in[5];
    const float* Wk   = (const float*)d_in[6];
    const float* Wv   = (const float*)d_in[7];
    const float* Wo   = (const float*)d_in[8];
    float* out = (float*)d_out;

    void *pxA, *pyA, *poA, *pWq, *pWk, *pWv, *pWo, *pQf, *pKf, *pVf, *pfl;
    cudaGetSymbolAddress(&pxA, g_xA);
    cudaGetSymbolAddress(&pyA, g_yA);
    cudaGetSymbolAddress(&poA, g_oA);
    cudaGetSymbolAddress(&pWq, g_WqB);
    cudaGetSymbolAddress(&pWk, g_WkB);
    cudaGetSymbolAddress(&pWv, g_WvB);
    cudaGetSymbolAddress(&pWo, g_WoB);
    cudaGetSymbolAddress(&pQf, g_Qf);
    cudaGetSymbolAddress(&pKf, g_Kf);
    cudaGetSymbolAddress(&pVf, g_Vf);
    cudaGetSymbolAddress(&pfl, g_flags);

    cudaFuncSetAttribute(gemm_qkv, cudaFuncAttributeMaxDynamicSharedMemorySize, GT_SMEM);
    cudaFuncSetAttribute(gemm_out, cudaFuncAttributeMaxDynamicSharedMemorySize, GT_SMEM);
    cudaFuncSetAttribute(attn_f16, cudaFuncAttributeMaxDynamicSharedMemorySize, AT_SMEM);

    prep_kernel<<<25600, 256>>>(x, y, Wq, Wk, Wv, Wo, mask,
                                (unsigned*)pxA, (unsigned*)pyA,
                                (unsigned*)pWq, (unsigned*)pWk,
                                (unsigned*)pWv, (unsigned*)pWo,
                                (int*)pfl);

    gemm_qkv<<<dim3(24, 32), 256, GT_SMEM>>>(
        (const uint4*)pxA, (const uint4*)pyA,
        (const uint4*)pWq, (const uint4*)pWk, (const uint4*)pWv,
        (unsigned*)pQf, (unsigned*)pKf, (unsigned*)pVf, cosb, sinb);

    attn_f16<<<dim3(T_ / 128, H_, B_), 256, AT_SMEM>>>(
        (const uint4*)pQf, (const uint4*)pKf, (const uint4*)pVf,
        mask, (const int*)pfl, (unsigned*)poA);

    gemm_out<<<dim3(8, 32), 256, GT_SMEM>>>(
        (const uint4*)poA, (const uint4*)pWo, out);
}